// round 1
// baseline (speedup 1.0000x reference)
#include <cuda_runtime.h>
#include <math.h>

#define Bb 4
#define Ss 4096
#define Aa 512
#define Hh 1024
#define NHh 16
#define HDd 64

// Scratch (device globals: allocation-free rule)
__device__ float g_q[(size_t)Bb * Ss * Hh];    // q, later reused as delta
__device__ float g_k[(size_t)Bb * Aa * Hh];
__device__ float g_v[(size_t)Bb * Aa * Hh];
__device__ float g_ctx[(size_t)Bb * Ss * Hh];

// ---------------------------------------------------------------------------
// C[M,1024] = A[M,1024] @ W[1024,1024]^T + bias, optionally * clamp(scale,0,0.3)
// 64x64 tile, BK=16, 256 threads, 4x4 per-thread microtile.
// ---------------------------------------------------------------------------
__global__ __launch_bounds__(256) void addmm_kernel(
    const float* __restrict__ Ag, const float* __restrict__ Wg,
    const float* __restrict__ bias, const float* __restrict__ scale_ptr,
    float* __restrict__ C)
{
    const int K = Hh;
    __shared__ float As[16][68];
    __shared__ float Ws[16][68];

    const int tid = threadIdx.x;
    const int bm = blockIdx.x * 64;
    const int bn = blockIdx.y * 64;

    const int lr = tid >> 2;          // 0..63 tile row
    const int lc = (tid & 3) << 2;    // 0,4,8,12 k offset
    const float* Ap = Ag + (size_t)(bm + lr) * K + lc;
    const float* Wp = Wg + (size_t)(bn + lr) * K + lc;

    const int tr = tid >> 4;          // 0..15
    const int tc = tid & 15;          // 0..15

    float acc[4][4] = {};

    for (int kk = 0; kk < K; kk += 16) {
        float4 av = *reinterpret_cast<const float4*>(Ap + kk);
        float4 wv = *reinterpret_cast<const float4*>(Wp + kk);
        As[lc + 0][lr] = av.x; As[lc + 1][lr] = av.y;
        As[lc + 2][lr] = av.z; As[lc + 3][lr] = av.w;
        Ws[lc + 0][lr] = wv.x; Ws[lc + 1][lr] = wv.y;
        Ws[lc + 2][lr] = wv.z; Ws[lc + 3][lr] = wv.w;
        __syncthreads();
        #pragma unroll
        for (int k = 0; k < 16; ++k) {
            float4 a = *reinterpret_cast<const float4*>(&As[k][tr * 4]);
            float4 w = *reinterpret_cast<const float4*>(&Ws[k][tc * 4]);
            acc[0][0] += a.x * w.x; acc[0][1] += a.x * w.y; acc[0][2] += a.x * w.z; acc[0][3] += a.x * w.w;
            acc[1][0] += a.y * w.x; acc[1][1] += a.y * w.y; acc[1][2] += a.y * w.z; acc[1][3] += a.y * w.w;
            acc[2][0] += a.z * w.x; acc[2][1] += a.z * w.y; acc[2][2] += a.z * w.z; acc[2][3] += a.z * w.w;
            acc[3][0] += a.w * w.x; acc[3][1] += a.w * w.y; acc[3][2] += a.w * w.z; acc[3][3] += a.w * w.w;
        }
        __syncthreads();
    }

    float scl = 1.0f;
    if (scale_ptr) {
        scl = *scale_ptr;
        scl = fminf(fmaxf(scl, 0.0f), 0.3f);
    }

    const float b0 = bias[bn + tc * 4 + 0];
    const float b1 = bias[bn + tc * 4 + 1];
    const float b2 = bias[bn + tc * 4 + 2];
    const float b3 = bias[bn + tc * 4 + 3];
    #pragma unroll
    for (int i = 0; i < 4; ++i) {
        float4 o;
        o.x = (acc[i][0] + b0) * scl;
        o.y = (acc[i][1] + b1) * scl;
        o.z = (acc[i][2] + b2) * scl;
        o.w = (acc[i][3] + b3) * scl;
        *reinterpret_cast<float4*>(&C[(size_t)(bm + tr * 4 + i) * K + bn + tc * 4]) = o;
    }
}

// ---------------------------------------------------------------------------
// Cross-attention: block = (32 queries) x (b, nh). 256 threads.
// 8 threads per query; keys streamed through smem in 128-key chunks.
// Online softmax; masked keys get logit -50 (exactly matches reference after
// its clip(where(mask, s, -1e4), -50, 50)).
// ---------------------------------------------------------------------------
__global__ __launch_bounds__(256) void attn_kernel(
    const int* __restrict__ amask, float* __restrict__ ctx)
{
    extern __shared__ float sm[];
    float* sQ = sm;                    // 32 * 68
    float* sK = sm + 32 * 68;          // 128 * 68
    float* sV = sK + 128 * 68;         // 128 * 68
    int*   sM = (int*)(sV + 128 * 68); // 128

    const int s0 = blockIdx.x * 32;
    const int nh = blockIdx.y;
    const int b  = blockIdx.z;
    const int tid = threadIdx.x;
    const int g  = tid >> 3;           // query within tile (0..31)
    const int si = tid & 7;            // slot within 8-thread group
    const int gw = (tid & 31) >> 3;    // group within warp (0..3)

    // Load Q tile: 32 rows x 64 floats
    for (int it = tid; it < 32 * 16; it += 256) {
        int r = it >> 4, c = it & 15;
        float4 qv = *reinterpret_cast<const float4*>(
            &g_q[(size_t)(b * Ss + s0 + r) * Hh + nh * HDd + c * 4]);
        *reinterpret_cast<float4*>(&sQ[r * 68 + c * 4]) = qv;
    }

    float m = -1e30f, l = 0.0f;
    float acc[8] = {0, 0, 0, 0, 0, 0, 0, 0};

    for (int ch = 0; ch < 4; ++ch) {
        __syncthreads();
        const int a0 = ch * 128;
        for (int it = tid; it < 128 * 16; it += 256) {
            int r = it >> 4, c = it & 15;
            size_t base = (size_t)(b * Aa + a0 + r) * Hh + nh * HDd + c * 4;
            *reinterpret_cast<float4*>(&sK[r * 68 + c * 4]) =
                *reinterpret_cast<const float4*>(&g_k[base]);
            *reinterpret_cast<float4*>(&sV[r * 68 + c * 4]) =
                *reinterpret_cast<const float4*>(&g_v[base]);
        }
        if (tid < 128) sM[tid] = amask[b * Aa + a0 + tid];
        __syncthreads();

        // Scores: each thread -> 16 keys (j = jj*8 + si) for its query g
        float s[16];
        float cmax = -1e30f;
        const float4* q4 = reinterpret_cast<const float4*>(&sQ[g * 68]);
        #pragma unroll
        for (int jj = 0; jj < 16; ++jj) {
            const int j = jj * 8 + si;
            const float4* k4 = reinterpret_cast<const float4*>(&sK[j * 68]);
            float dot = 0.0f;
            #pragma unroll
            for (int d = 0; d < 16; ++d) {
                float4 a = q4[d];
                float4 k = k4[d];
                dot += a.x * k.x + a.y * k.y + a.z * k.z + a.w * k.w;
            }
            float sc = dot * 0.125f;
            sc = fminf(fmaxf(sc, -50.0f), 50.0f);
            if (sM[j] <= 0) sc = -50.0f;
            s[jj] = sc;
            cmax = fmaxf(cmax, sc);
        }
        #pragma unroll
        for (int o = 4; o; o >>= 1)
            cmax = fmaxf(cmax, __shfl_xor_sync(0xffffffffu, cmax, o));

        const float nm = fmaxf(m, cmax);
        const float corr = __expf(m - nm);
        l *= corr;
        #pragma unroll
        for (int d = 0; d < 8; ++d) acc[d] *= corr;

        float ps = 0.0f;
        #pragma unroll
        for (int jj = 0; jj < 16; ++jj) {
            float p = __expf(s[jj] - nm);
            s[jj] = p;
            ps += p;
        }
        #pragma unroll
        for (int o = 4; o; o >>= 1)
            ps += __shfl_xor_sync(0xffffffffu, ps, o);
        l += ps;
        m = nm;

        // Accumulate P @ V. Thread handles dims [4si..4si+3] and [32+4si..].
        #pragma unroll
        for (int jj = 0; jj < 16; ++jj) {
            const float pj = s[jj];
            #pragma unroll
            for (int r = 0; r < 8; ++r) {
                const float p = __shfl_sync(0xffffffffu, pj, gw * 8 + r);
                const int j = jj * 8 + r;
                const float4* v4 = reinterpret_cast<const float4*>(&sV[j * 68]);
                float4 v0 = v4[si];
                float4 v1 = v4[8 + si];
                acc[0] += p * v0.x; acc[1] += p * v0.y;
                acc[2] += p * v0.z; acc[3] += p * v0.w;
                acc[4] += p * v1.x; acc[5] += p * v1.y;
                acc[6] += p * v1.z; acc[7] += p * v1.w;
            }
        }
    }

    const float inv = 1.0f / l;
    float4 o0 = make_float4(acc[0] * inv, acc[1] * inv, acc[2] * inv, acc[3] * inv);
    float4 o1 = make_float4(acc[4] * inv, acc[5] * inv, acc[6] * inv, acc[7] * inv);
    const size_t base = (size_t)(b * Ss + s0 + g) * Hh + nh * HDd;
    *reinterpret_cast<float4*>(&ctx[base + 4 * si]) = o0;
    *reinterpret_cast<float4*>(&ctx[base + 32 + 4 * si]) = o1;
}

// ---------------------------------------------------------------------------
// Row LayerNorm over H=1024: block per row, 256 threads, float4 per thread.
// ---------------------------------------------------------------------------
__global__ __launch_bounds__(256) void ln_kernel(
    const float* __restrict__ X, const float* __restrict__ gamma,
    const float* __restrict__ beta, float* __restrict__ out)
{
    __shared__ float red[8];
    const int row = blockIdx.x;
    const int tid = threadIdx.x;

    const float4 v = reinterpret_cast<const float4*>(X + (size_t)row * Hh)[tid];
    float sum = v.x + v.y + v.z + v.w;
    #pragma unroll
    for (int o = 16; o; o >>= 1) sum += __shfl_xor_sync(0xffffffffu, sum, o);
    if ((tid & 31) == 0) red[tid >> 5] = sum;
    __syncthreads();
    float tot = 0.0f;
    #pragma unroll
    for (int i = 0; i < 8; ++i) tot += red[i];
    const float mu = tot * (1.0f / Hh);

    const float dx = v.x - mu, dy = v.y - mu, dz = v.z - mu, dw = v.w - mu;
    float sq = dx * dx + dy * dy + dz * dz + dw * dw;
    #pragma unroll
    for (int o = 16; o; o >>= 1) sq += __shfl_xor_sync(0xffffffffu, sq, o);
    __syncthreads();
    if ((tid & 31) == 0) red[tid >> 5] = sq;
    __syncthreads();
    float tot2 = 0.0f;
    #pragma unroll
    for (int i = 0; i < 8; ++i) tot2 += red[i];
    const float var = tot2 * (1.0f / Hh);
    const float rstd = rsqrtf(var + 1e-5f);

    const float4 gm = reinterpret_cast<const float4*>(gamma)[tid];
    const float4 bt = reinterpret_cast<const float4*>(beta)[tid];
    float4 o;
    o.x = dx * rstd * gm.x + bt.x;
    o.y = dy * rstd * gm.y + bt.y;
    o.z = dz * rstd * gm.z + bt.z;
    o.w = dw * rstd * gm.w + bt.w;
    reinterpret_cast<float4*>(out + (size_t)row * Hh)[tid] = o;
}

// ---------------------------------------------------------------------------
extern "C" void kernel_launch(void* const* d_in, const int* in_sizes, int n_in,
                              void* d_out, int out_size)
{
    const float* hs    = (const float*)d_in[0];
    const float* at    = (const float*)d_in[1];
    const int*   am    = (const int*)d_in[2];
    const float* Wq    = (const float*)d_in[3];
    const float* bq    = (const float*)d_in[4];
    const float* Wk    = (const float*)d_in[5];
    const float* bk    = (const float*)d_in[6];
    const float* Wv    = (const float*)d_in[7];
    const float* bv    = (const float*)d_in[8];
    const float* Wo    = (const float*)d_in[9];
    const float* bo    = (const float*)d_in[10];
    const float* gamma = (const float*)d_in[11];
    const float* beta  = (const float*)d_in[12];
    const float* rs    = (const float*)d_in[13];
    float* out = (float*)d_out;

    float *q, *k, *v, *ctx;
    cudaGetSymbolAddress((void**)&q,   g_q);
    cudaGetSymbolAddress((void**)&k,   g_k);
    cudaGetSymbolAddress((void**)&v,   g_v);
    cudaGetSymbolAddress((void**)&ctx, g_ctx);

    const dim3 blk(256);

    // Projections
    addmm_kernel<<<dim3((Bb * Ss) / 64, Hh / 64), blk>>>(hs, Wq, bq, nullptr, q);
    addmm_kernel<<<dim3((Bb * Aa) / 64, Hh / 64), blk>>>(at, Wk, bk, nullptr, k);
    addmm_kernel<<<dim3((Bb * Aa) / 64, Hh / 64), blk>>>(at, Wv, bv, nullptr, v);

    // Attention
    size_t shmem = (size_t)(32 * 68 + 2 * 128 * 68) * sizeof(float) + 128 * sizeof(int);
    cudaFuncSetAttribute(attn_kernel, cudaFuncAttributeMaxDynamicSharedMemorySize, (int)shmem);
    attn_kernel<<<dim3(Ss / 32, NHh, Bb), blk, shmem>>>(am, ctx);

    // Output projection (+bias, * clamp(rs,0,0.3)) into reused q buffer
    addmm_kernel<<<dim3((Bb * Ss) / 64, Hh / 64), blk>>>(ctx, Wo, bo, rs, q);

    // LayerNorm -> final output
    ln_kernel<<<dim3(Bb * Ss), blk>>>(q, gamma, beta, out);
}

// round 2
// speedup vs baseline: 1.5920x; 1.5920x over previous
#include <cuda_runtime.h>
#include <math.h>
#include <stdint.h>

#define Bb 4
#define Ss 4096
#define Aa 512
#define Hh 1024
#define NHh 16
#define HDd 64

// Scratch (device globals: allocation-free rule)
__device__ float g_q[(size_t)Bb * Ss * Hh];    // q, later reused as delta
__device__ float g_k[(size_t)Bb * Aa * Hh];
__device__ float g_v[(size_t)Bb * Aa * Hh];
__device__ float g_ctx[(size_t)Bb * Ss * Hh];

// ---------------------------------------------------------------------------
// Helpers
// ---------------------------------------------------------------------------
__device__ __forceinline__ void cp_async16(uint32_t s, const void* g) {
    asm volatile("cp.async.cg.shared.global [%0], [%1], 16;" :: "r"(s), "l"(g));
}
__device__ __forceinline__ void cp_commit() {
    asm volatile("cp.async.commit_group;");
}
__device__ __forceinline__ void cp_wait0() {
    asm volatile("cp.async.wait_group 0;");
}
__device__ __forceinline__ uint32_t f2tf32(float f) {
    uint32_t u;
    asm("cvt.rna.tf32.f32 %0, %1;" : "=r"(u) : "f"(f));
    return u;
}
__device__ __forceinline__ void mma_tf32(float* d, const uint32_t* a, const uint32_t* b) {
    asm volatile(
        "mma.sync.aligned.m16n8k8.row.col.f32.tf32.tf32.f32 "
        "{%0,%1,%2,%3}, {%4,%5,%6,%7}, {%8,%9}, {%0,%1,%2,%3};"
        : "+f"(d[0]), "+f"(d[1]), "+f"(d[2]), "+f"(d[3])
        : "r"(a[0]), "r"(a[1]), "r"(a[2]), "r"(a[3]), "r"(b[0]), "r"(b[1]));
}

// ---------------------------------------------------------------------------
// C[M,1024] = A[M,1024] @ W[1024,1024]^T + bias, optionally * clamp(scale,0,0.3)
// tf32 mma.sync, 128x128 block tile, BK=32, 256 threads (8 warps, 2m x 4n),
// warp tile 64x32, double-buffered cp.async.
// Smem row stride 36 floats -> fragment LDS banks (4r+c)%32: conflict-free.
// ---------------------------------------------------------------------------
#define KSTR 36
#define STAGE_F (128 * KSTR)   // floats per matrix per stage

__global__ __launch_bounds__(256, 2) void addmm_tf32(
    const float* __restrict__ Ag, const float* __restrict__ Wg,
    const float* __restrict__ bias, const float* __restrict__ scale_ptr,
    float* __restrict__ C)
{
    extern __shared__ float smf[];
    const int K = 1024;
    const int tid  = threadIdx.x;
    const int lane = tid & 31;
    const int wid  = tid >> 5;
    const int wm   = wid & 1;    // 0..1 -> 64-row slab
    const int wn   = wid >> 1;   // 0..3 -> 32-col slab
    const int bm   = blockIdx.x * 128;
    const int bn   = blockIdx.y * 128;

    // global->smem mapping: 8 lanes cover 32 consecutive k floats (128B)
    const int kv = tid & 7;      // float4 index within 32-k chunk
    const int rg = tid >> 3;     // 0..31 base row

    const float* Aptr = Ag + (size_t)(bm + rg) * K + kv * 4;
    const float* Wptr = Wg + (size_t)(bn + rg) * K + kv * 4;

    const uint32_t sA = (uint32_t)__cvta_generic_to_shared(smf);
    const uint32_t sB = sA + 2u * STAGE_F * 4u;

    auto issue = [&](int kt, int buf) {
        const int kk = kt * 32;
        const uint32_t a_s = sA + (uint32_t)buf * STAGE_F * 4u;
        const uint32_t b_s = sB + (uint32_t)buf * STAGE_F * 4u;
        #pragma unroll
        for (int j = 0; j < 4; ++j) {
            const int row = rg + j * 32;
            cp_async16(a_s + (uint32_t)(row * KSTR + kv * 4) * 4u,
                       Aptr + (size_t)j * 32 * K + kk);
            cp_async16(b_s + (uint32_t)(row * KSTR + kv * 4) * 4u,
                       Wptr + (size_t)j * 32 * K + kk);
        }
    };

    float acc[4][4][4] = {};

    issue(0, 0);
    cp_commit();

    const int KT = K / 32;  // 32
    for (int kt = 0; kt < KT; ++kt) {
        cp_wait0();
        __syncthreads();
        if (kt + 1 < KT) {
            issue(kt + 1, (kt + 1) & 1);
            cp_commit();
        }
        const float* As = smf + (kt & 1) * STAGE_F;
        const float* Bs = smf + 2 * STAGE_F + (kt & 1) * STAGE_F;
        const int r = lane >> 2, c = lane & 3;

        #pragma unroll
        for (int ks = 0; ks < 4; ++ks) {
            uint32_t a[4][4], b[4][2];
            #pragma unroll
            for (int mt = 0; mt < 4; ++mt) {
                const float* base = As + (wm * 64 + mt * 16 + r) * KSTR + ks * 8 + c;
                a[mt][0] = f2tf32(base[0]);
                a[mt][1] = f2tf32(base[8 * KSTR]);
                a[mt][2] = f2tf32(base[4]);
                a[mt][3] = f2tf32(base[8 * KSTR + 4]);
            }
            #pragma unroll
            for (int nt = 0; nt < 4; ++nt) {
                const float* base = Bs + (wn * 32 + nt * 8 + r) * KSTR + ks * 8 + c;
                b[nt][0] = f2tf32(base[0]);
                b[nt][1] = f2tf32(base[4]);
            }
            #pragma unroll
            for (int mt = 0; mt < 4; ++mt)
                #pragma unroll
                for (int nt = 0; nt < 4; ++nt)
                    mma_tf32(acc[mt][nt], a[mt], b[nt]);
        }
        __syncthreads();
    }

    float scl = 1.0f;
    if (scale_ptr) scl = fminf(fmaxf(*scale_ptr, 0.0f), 0.3f);

    const int r = lane >> 2;
    const int c2 = (lane & 3) * 2;
    #pragma unroll
    for (int mt = 0; mt < 4; ++mt) {
        const int row0 = bm + wm * 64 + mt * 16 + r;
        #pragma unroll
        for (int nt = 0; nt < 4; ++nt) {
            const int col = bn + wn * 32 + nt * 8 + c2;
            const float b0 = bias[col], b1 = bias[col + 1];
            float2 v0 = make_float2((acc[mt][nt][0] + b0) * scl,
                                    (acc[mt][nt][1] + b1) * scl);
            float2 v1 = make_float2((acc[mt][nt][2] + b0) * scl,
                                    (acc[mt][nt][3] + b1) * scl);
            *reinterpret_cast<float2*>(&C[(size_t)row0 * 1024 + col]) = v0;
            *reinterpret_cast<float2*>(&C[(size_t)(row0 + 8) * 1024 + col]) = v1;
        }
    }
}

// ---------------------------------------------------------------------------
// Cross-attention: block = (32 queries) x (b, nh). 256 threads. (unchanged)
// ---------------------------------------------------------------------------
__global__ __launch_bounds__(256) void attn_kernel(
    const int* __restrict__ amask, float* __restrict__ ctx)
{
    extern __shared__ float sm[];
    float* sQ = sm;                    // 32 * 68
    float* sK = sm + 32 * 68;          // 128 * 68
    float* sV = sK + 128 * 68;         // 128 * 68
    int*   sM = (int*)(sV + 128 * 68); // 128

    const int s0 = blockIdx.x * 32;
    const int nh = blockIdx.y;
    const int b  = blockIdx.z;
    const int tid = threadIdx.x;
    const int g  = tid >> 3;
    const int si = tid & 7;
    const int gw = (tid & 31) >> 3;

    for (int it = tid; it < 32 * 16; it += 256) {
        int r = it >> 4, c = it & 15;
        float4 qv = *reinterpret_cast<const float4*>(
            &g_q[(size_t)(b * Ss + s0 + r) * Hh + nh * HDd + c * 4]);
        *reinterpret_cast<float4*>(&sQ[r * 68 + c * 4]) = qv;
    }

    float m = -1e30f, l = 0.0f;
    float acc[8] = {0, 0, 0, 0, 0, 0, 0, 0};

    for (int ch = 0; ch < 4; ++ch) {
        __syncthreads();
        const int a0 = ch * 128;
        for (int it = tid; it < 128 * 16; it += 256) {
            int r = it >> 4, c = it & 15;
            size_t base = (size_t)(b * Aa + a0 + r) * Hh + nh * HDd + c * 4;
            *reinterpret_cast<float4*>(&sK[r * 68 + c * 4]) =
                *reinterpret_cast<const float4*>(&g_k[base]);
            *reinterpret_cast<float4*>(&sV[r * 68 + c * 4]) =
                *reinterpret_cast<const float4*>(&g_v[base]);
        }
        if (tid < 128) sM[tid] = amask[b * Aa + a0 + tid];
        __syncthreads();

        float s[16];
        float cmax = -1e30f;
        const float4* q4 = reinterpret_cast<const float4*>(&sQ[g * 68]);
        #pragma unroll
        for (int jj = 0; jj < 16; ++jj) {
            const int j = jj * 8 + si;
            const float4* k4 = reinterpret_cast<const float4*>(&sK[j * 68]);
            float dot = 0.0f;
            #pragma unroll
            for (int d = 0; d < 16; ++d) {
                float4 a = q4[d];
                float4 k = k4[d];
                dot += a.x * k.x + a.y * k.y + a.z * k.z + a.w * k.w;
            }
            float sc = dot * 0.125f;
            sc = fminf(fmaxf(sc, -50.0f), 50.0f);
            if (sM[j] <= 0) sc = -50.0f;
            s[jj] = sc;
            cmax = fmaxf(cmax, sc);
        }
        #pragma unroll
        for (int o = 4; o; o >>= 1)
            cmax = fmaxf(cmax, __shfl_xor_sync(0xffffffffu, cmax, o));

        const float nm = fmaxf(m, cmax);
        const float corr = __expf(m - nm);
        l *= corr;
        #pragma unroll
        for (int d = 0; d < 8; ++d) acc[d] *= corr;

        float ps = 0.0f;
        #pragma unroll
        for (int jj = 0; jj < 16; ++jj) {
            float p = __expf(s[jj] - nm);
            s[jj] = p;
            ps += p;
        }
        #pragma unroll
        for (int o = 4; o; o >>= 1)
            ps += __shfl_xor_sync(0xffffffffu, ps, o);
        l += ps;
        m = nm;

        #pragma unroll
        for (int jj = 0; jj < 16; ++jj) {
            const float pj = s[jj];
            #pragma unroll
            for (int r = 0; r < 8; ++r) {
                const float p = __shfl_sync(0xffffffffu, pj, gw * 8 + r);
                const int j = jj * 8 + r;
                const float4* v4 = reinterpret_cast<const float4*>(&sV[j * 68]);
                float4 v0 = v4[si];
                float4 v1 = v4[8 + si];
                acc[0] += p * v0.x; acc[1] += p * v0.y;
                acc[2] += p * v0.z; acc[3] += p * v0.w;
                acc[4] += p * v1.x; acc[5] += p * v1.y;
                acc[6] += p * v1.z; acc[7] += p * v1.w;
            }
        }
    }

    const float inv = 1.0f / l;
    float4 o0 = make_float4(acc[0] * inv, acc[1] * inv, acc[2] * inv, acc[3] * inv);
    float4 o1 = make_float4(acc[4] * inv, acc[5] * inv, acc[6] * inv, acc[7] * inv);
    const size_t base = (size_t)(b * Ss + s0 + g) * Hh + nh * HDd;
    *reinterpret_cast<float4*>(&ctx[base + 4 * si]) = o0;
    *reinterpret_cast<float4*>(&ctx[base + 32 + 4 * si]) = o1;
}

// ---------------------------------------------------------------------------
// Row LayerNorm over H=1024 (unchanged)
// ---------------------------------------------------------------------------
__global__ __launch_bounds__(256) void ln_kernel(
    const float* __restrict__ X, const float* __restrict__ gamma,
    const float* __restrict__ beta, float* __restrict__ out)
{
    __shared__ float red[8];
    const int row = blockIdx.x;
    const int tid = threadIdx.x;

    const float4 v = reinterpret_cast<const float4*>(X + (size_t)row * Hh)[tid];
    float sum = v.x + v.y + v.z + v.w;
    #pragma unroll
    for (int o = 16; o; o >>= 1) sum += __shfl_xor_sync(0xffffffffu, sum, o);
    if ((tid & 31) == 0) red[tid >> 5] = sum;
    __syncthreads();
    float tot = 0.0f;
    #pragma unroll
    for (int i = 0; i < 8; ++i) tot += red[i];
    const float mu = tot * (1.0f / Hh);

    const float dx = v.x - mu, dy = v.y - mu, dz = v.z - mu, dw = v.w - mu;
    float sq = dx * dx + dy * dy + dz * dz + dw * dw;
    #pragma unroll
    for (int o = 16; o; o >>= 1) sq += __shfl_xor_sync(0xffffffffu, sq, o);
    __syncthreads();
    if ((tid & 31) == 0) red[tid >> 5] = sq;
    __syncthreads();
    float tot2 = 0.0f;
    #pragma unroll
    for (int i = 0; i < 8; ++i) tot2 += red[i];
    const float var = tot2 * (1.0f / Hh);
    const float rstd = rsqrtf(var + 1e-5f);

    const float4 gm = reinterpret_cast<const float4*>(gamma)[tid];
    const float4 bt = reinterpret_cast<const float4*>(beta)[tid];
    float4 o;
    o.x = dx * rstd * gm.x + bt.x;
    o.y = dy * rstd * gm.y + bt.y;
    o.z = dz * rstd * gm.z + bt.z;
    o.w = dw * rstd * gm.w + bt.w;
    reinterpret_cast<float4*>(out + (size_t)row * Hh)[tid] = o;
}

// ---------------------------------------------------------------------------
extern "C" void kernel_launch(void* const* d_in, const int* in_sizes, int n_in,
                              void* d_out, int out_size)
{
    const float* hs    = (const float*)d_in[0];
    const float* at    = (const float*)d_in[1];
    const int*   am    = (const int*)d_in[2];
    const float* Wq    = (const float*)d_in[3];
    const float* bq    = (const float*)d_in[4];
    const float* Wk    = (const float*)d_in[5];
    const float* bk    = (const float*)d_in[6];
    const float* Wv    = (const float*)d_in[7];
    const float* bv    = (const float*)d_in[8];
    const float* Wo    = (const float*)d_in[9];
    const float* bo    = (const float*)d_in[10];
    const float* gamma = (const float*)d_in[11];
    const float* beta  = (const float*)d_in[12];
    const float* rs    = (const float*)d_in[13];
    float* out = (float*)d_out;

    float *q, *k, *v, *ctx;
    cudaGetSymbolAddress((void**)&q,   g_q);
    cudaGetSymbolAddress((void**)&k,   g_k);
    cudaGetSymbolAddress((void**)&v,   g_v);
    cudaGetSymbolAddress((void**)&ctx, g_ctx);

    const dim3 blk(256);

    // tf32 GEMM smem: 4 stages-worth = 4 * 128*36 floats = 72 KB
    const int gemm_smem = 4 * STAGE_F * sizeof(float);
    static int attr_done = 0;
    if (!attr_done) {
        cudaFuncSetAttribute(addmm_tf32, cudaFuncAttributeMaxDynamicSharedMemorySize, gemm_smem);
        attr_done = 1;
    }

    // Projections
    addmm_tf32<<<dim3((Bb * Ss) / 128, Hh / 128), blk, gemm_smem>>>(hs, Wq, bq, nullptr, q);
    addmm_tf32<<<dim3((Bb * Aa) / 128, Hh / 128), blk, gemm_smem>>>(at, Wk, bk, nullptr, k);
    addmm_tf32<<<dim3((Bb * Aa) / 128, Hh / 128), blk, gemm_smem>>>(at, Wv, bv, nullptr, v);

    // Attention
    size_t shmem = (size_t)(32 * 68 + 2 * 128 * 68) * sizeof(float) + 128 * sizeof(int);
    cudaFuncSetAttribute(attn_kernel, cudaFuncAttributeMaxDynamicSharedMemorySize, (int)shmem);
    attn_kernel<<<dim3(Ss / 32, NHh, Bb), blk, shmem>>>(am, ctx);

    // Output projection (+bias, * clamp(rs,0,0.3)) into reused q buffer
    addmm_tf32<<<dim3((Bb * Ss) / 128, Hh / 128), blk, gemm_smem>>>(ctx, Wo, bo, rs, q);

    // LayerNorm -> final output
    ln_kernel<<<dim3(Bb * Ss), blk>>>(q, gamma, beta, out);
}

// round 3
// speedup vs baseline: 3.5471x; 2.2280x over previous
#include <cuda_runtime.h>
#include <math.h>
#include <stdint.h>

#define Bb 4
#define Ss 4096
#define Aa 512
#define Hh 1024
#define NHh 16
#define HDd 64

// Scratch (device globals: allocation-free rule)
__device__ float g_q[(size_t)Bb * Ss * Hh];    // q, later reused as delta
__device__ float g_k[(size_t)Bb * Aa * Hh];
__device__ float g_v[(size_t)Bb * Aa * Hh];
__device__ float g_ctx[(size_t)Bb * Ss * Hh];

// ---------------------------------------------------------------------------
// Helpers
// ---------------------------------------------------------------------------
__device__ __forceinline__ void cp_async16(uint32_t s, const void* g) {
    asm volatile("cp.async.cg.shared.global [%0], [%1], 16;" :: "r"(s), "l"(g));
}
__device__ __forceinline__ void cp_commit() {
    asm volatile("cp.async.commit_group;");
}
__device__ __forceinline__ void cp_wait0() {
    asm volatile("cp.async.wait_group 0;");
}
__device__ __forceinline__ void cp_wait1() {
    asm volatile("cp.async.wait_group 1;");
}
__device__ __forceinline__ uint32_t f2tf32(float f) {
    uint32_t u;
    asm("cvt.rna.tf32.f32 %0, %1;" : "=r"(u) : "f"(f));
    return u;
}
__device__ __forceinline__ void mma_tf32(float* d, const uint32_t* a, const uint32_t* b) {
    asm volatile(
        "mma.sync.aligned.m16n8k8.row.col.f32.tf32.tf32.f32 "
        "{%0,%1,%2,%3}, {%4,%5,%6,%7}, {%8,%9}, {%0,%1,%2,%3};"
        : "+f"(d[0]), "+f"(d[1]), "+f"(d[2]), "+f"(d[3])
        : "r"(a[0]), "r"(a[1]), "r"(a[2]), "r"(a[3]), "r"(b[0]), "r"(b[1]));
}

// ---------------------------------------------------------------------------
// addmm: C[M,1024] = A[M,1024] @ W[1024,1024]^T + bias (optional *clamp(rs))
// tf32 mma.sync, 128x128 tile, BK=32, 8 warps (64x32 warp tile), dbuf cp.async
// ---------------------------------------------------------------------------
#define KSTR 36
#define STAGE_F (128 * KSTR)

__global__ __launch_bounds__(256, 2) void addmm_tf32(
    const float* __restrict__ Ag, const float* __restrict__ Wg,
    const float* __restrict__ bias, const float* __restrict__ scale_ptr,
    float* __restrict__ C)
{
    extern __shared__ float smf[];
    const int K = 1024;
    const int tid  = threadIdx.x;
    const int lane = tid & 31;
    const int wid  = tid >> 5;
    const int wm   = wid & 1;
    const int wn   = wid >> 1;
    const int bm   = blockIdx.x * 128;
    const int bn   = blockIdx.y * 128;

    const int kv = tid & 7;
    const int rg = tid >> 3;

    const float* Aptr = Ag + (size_t)(bm + rg) * K + kv * 4;
    const float* Wptr = Wg + (size_t)(bn + rg) * K + kv * 4;

    const uint32_t sA = (uint32_t)__cvta_generic_to_shared(smf);
    const uint32_t sB = sA + 2u * STAGE_F * 4u;

    auto issue = [&](int kt, int buf) {
        const int kk = kt * 32;
        const uint32_t a_s = sA + (uint32_t)buf * STAGE_F * 4u;
        const uint32_t b_s = sB + (uint32_t)buf * STAGE_F * 4u;
        #pragma unroll
        for (int j = 0; j < 4; ++j) {
            const int row = rg + j * 32;
            cp_async16(a_s + (uint32_t)(row * KSTR + kv * 4) * 4u,
                       Aptr + (size_t)j * 32 * K + kk);
            cp_async16(b_s + (uint32_t)(row * KSTR + kv * 4) * 4u,
                       Wptr + (size_t)j * 32 * K + kk);
        }
    };

    float acc[4][4][4] = {};

    issue(0, 0);
    cp_commit();

    const int KT = K / 32;
    for (int kt = 0; kt < KT; ++kt) {
        cp_wait0();
        __syncthreads();
        if (kt + 1 < KT) {
            issue(kt + 1, (kt + 1) & 1);
            cp_commit();
        }
        const float* As = smf + (kt & 1) * STAGE_F;
        const float* Bs = smf + 2 * STAGE_F + (kt & 1) * STAGE_F;
        const int r = lane >> 2, c = lane & 3;

        #pragma unroll
        for (int ks = 0; ks < 4; ++ks) {
            uint32_t a[4][4], b[4][2];
            #pragma unroll
            for (int mt = 0; mt < 4; ++mt) {
                const float* base = As + (wm * 64 + mt * 16 + r) * KSTR + ks * 8 + c;
                a[mt][0] = f2tf32(base[0]);
                a[mt][1] = f2tf32(base[8 * KSTR]);
                a[mt][2] = f2tf32(base[4]);
                a[mt][3] = f2tf32(base[8 * KSTR + 4]);
            }
            #pragma unroll
            for (int nt = 0; nt < 4; ++nt) {
                const float* base = Bs + (wn * 32 + nt * 8 + r) * KSTR + ks * 8 + c;
                b[nt][0] = f2tf32(base[0]);
                b[nt][1] = f2tf32(base[4]);
            }
            #pragma unroll
            for (int mt = 0; mt < 4; ++mt)
                #pragma unroll
                for (int nt = 0; nt < 4; ++nt)
                    mma_tf32(acc[mt][nt], a[mt], b[nt]);
        }
        __syncthreads();
    }

    float scl = 1.0f;
    if (scale_ptr) scl = fminf(fmaxf(*scale_ptr, 0.0f), 0.3f);

    const int r = lane >> 2;
    const int c2 = (lane & 3) * 2;
    #pragma unroll
    for (int mt = 0; mt < 4; ++mt) {
        const int row0 = bm + wm * 64 + mt * 16 + r;
        #pragma unroll
        for (int nt = 0; nt < 4; ++nt) {
            const int col = bn + wn * 32 + nt * 8 + c2;
            const float b0 = bias[col], b1 = bias[col + 1];
            float2 v0 = make_float2((acc[mt][nt][0] + b0) * scl,
                                    (acc[mt][nt][1] + b1) * scl);
            float2 v1 = make_float2((acc[mt][nt][2] + b0) * scl,
                                    (acc[mt][nt][3] + b1) * scl);
            *reinterpret_cast<float2*>(&C[(size_t)row0 * 1024 + col]) = v0;
            *reinterpret_cast<float2*>(&C[(size_t)(row0 + 8) * 1024 + col]) = v1;
        }
    }
}

// ---------------------------------------------------------------------------
// Tensor-core flash attention.
// Block = 128 queries x 1 head: 8 warps, warp = 16 queries.
// K/V in 64-key chunks, double-buffered cp.async. QK^T in tf32x3 (fp32-grade
// scores), softmax online, PV in tf32. P goes through per-warp smem to fix
// the D-fragment -> A-fragment layout. Smem stride 68 -> conflict-free frags.
// ---------------------------------------------------------------------------
#define QSTR 68
#define KVCH 64

__global__ __launch_bounds__(256) void attn_mma(
    const int* __restrict__ amask, float* __restrict__ ctx)
{
    extern __shared__ float sm[];
    float* sQ = sm;                              // 128*68 floats (reused as sP)
    float* sKb = sm + 128 * QSTR;                // 2 * 64*68
    float* sVb = sKb + 2 * KVCH * QSTR;          // 2 * 64*68
    int*   sMi = (int*)(sVb + 2 * KVCH * QSTR);  // 2 * 64 ints

    const int s0  = blockIdx.x * 128;
    const int nh  = blockIdx.y;
    const int b   = blockIdx.z;
    const int tid = threadIdx.x;
    const int lane = tid & 31;
    const int wid  = tid >> 5;
    const int r = lane >> 2;
    const int c = lane & 3;

    const uint32_t sQa = (uint32_t)__cvta_generic_to_shared(sQ);
    const uint32_t sKa = (uint32_t)__cvta_generic_to_shared(sKb);
    const uint32_t sVa = (uint32_t)__cvta_generic_to_shared(sVb);
    const uint32_t sMa = (uint32_t)__cvta_generic_to_shared(sMi);

    // ---- issue Q tile load (group 0): 128 rows x 16 float4 ----
    #pragma unroll
    for (int i = 0; i < 8; ++i) {
        const int it = tid + i * 256;
        const int row = it >> 4, col = it & 15;
        cp_async16(sQa + (uint32_t)(row * QSTR + col * 4) * 4u,
                   &g_q[(size_t)(b * Ss + s0 + row) * Hh + nh * HDd + col * 4]);
    }
    cp_commit();

    auto load_kv = [&](int ch, int buf) {
        const int a0 = ch * KVCH;
        const uint32_t ko = sKa + (uint32_t)buf * KVCH * QSTR * 4u;
        const uint32_t vo = sVa + (uint32_t)buf * KVCH * QSTR * 4u;
        #pragma unroll
        for (int i = 0; i < 4; ++i) {
            const int it = tid + i * 256;
            const int row = it >> 4, col = it & 15;
            const size_t g = (size_t)(b * Aa + a0 + row) * Hh + nh * HDd + col * 4;
            cp_async16(ko + (uint32_t)(row * QSTR + col * 4) * 4u, &g_k[g]);
            cp_async16(vo + (uint32_t)(row * QSTR + col * 4) * 4u, &g_v[g]);
        }
        if (tid < 16)
            cp_async16(sMa + (uint32_t)buf * 256u + tid * 16u,
                       &amask[b * Aa + a0 + tid * 4]);
    };

    load_kv(0, 0);   // group 1
    cp_commit();

    cp_wait1();      // Q ready
    __syncthreads();

    // ---- build Q fragments (hi/lo split for tf32x3) ----
    uint32_t qh[8][4], ql[8][4];
    {
        const float* qb = sQ + (wid * 16) * QSTR;
        #pragma unroll
        for (int kt = 0; kt < 8; ++kt) {
            #pragma unroll
            for (int j = 0; j < 4; ++j) {
                const int rr = r + (j & 1) * 8;
                const int cc = kt * 8 + c + (j >> 1) * 4;
                const float f = qb[rr * QSTR + cc];
                const uint32_t hi = f2tf32(f);
                qh[kt][j] = hi;
                ql[kt][j] = f2tf32(f - __uint_as_float(hi));
            }
        }
    }
    __syncthreads();   // all warps done reading sQ; region becomes sP

    float m0 = -1e30f, m1 = -1e30f, l0 = 0.0f, l1 = 0.0f;
    float o[8][4] = {};
    float* sP = sQ + (wid * 16) * QSTR;   // per-warp private 16x68 region

    for (int ch = 0; ch < 8; ++ch) {
        const int buf = ch & 1;
        cp_wait0();
        __syncthreads();
        if (ch < 7) { load_kv(ch + 1, buf ^ 1); cp_commit(); }

        const float* bK = sKb + buf * KVCH * QSTR;
        const float* bV = sVb + buf * KVCH * QSTR;
        const int*   bM = sMi + buf * KVCH;

        // ---- S = Q K^T (tf32x3) ----
        float s[8][4] = {};
        #pragma unroll
        for (int kt = 0; kt < 8; ++kt) {
            #pragma unroll
            for (int nt = 0; nt < 8; ++nt) {
                const float f0 = bK[(nt * 8 + r) * QSTR + kt * 8 + c];
                const float f1 = bK[(nt * 8 + r) * QSTR + kt * 8 + c + 4];
                const uint32_t h0 = f2tf32(f0);
                const uint32_t h1 = f2tf32(f1);
                uint32_t bh[2] = { h0, h1 };
                uint32_t bl[2] = { f2tf32(f0 - __uint_as_float(h0)),
                                   f2tf32(f1 - __uint_as_float(h1)) };
                mma_tf32(s[nt], qh[kt], bh);
                mma_tf32(s[nt], qh[kt], bl);
                mma_tf32(s[nt], ql[kt], bh);
            }
        }

        // ---- scale + clip + mask, row maxima ----
        float rm0 = -1e30f, rm1 = -1e30f;
        #pragma unroll
        for (int nt = 0; nt < 8; ++nt) {
            const int mk0 = bM[nt * 8 + 2 * c];
            const int mk1 = bM[nt * 8 + 2 * c + 1];
            #pragma unroll
            for (int j = 0; j < 4; ++j) {
                float sc = fminf(fmaxf(s[nt][j] * 0.125f, -50.0f), 50.0f);
                const int mk = (j & 1) ? mk1 : mk0;
                if (mk <= 0) sc = -50.0f;
                s[nt][j] = sc;
            }
            rm0 = fmaxf(rm0, fmaxf(s[nt][0], s[nt][1]));
            rm1 = fmaxf(rm1, fmaxf(s[nt][2], s[nt][3]));
        }
        rm0 = fmaxf(rm0, __shfl_xor_sync(0xffffffffu, rm0, 1));
        rm0 = fmaxf(rm0, __shfl_xor_sync(0xffffffffu, rm0, 2));
        rm1 = fmaxf(rm1, __shfl_xor_sync(0xffffffffu, rm1, 1));
        rm1 = fmaxf(rm1, __shfl_xor_sync(0xffffffffu, rm1, 2));

        const float nm0 = fmaxf(m0, rm0);
        const float nm1 = fmaxf(m1, rm1);
        const float corr0 = __expf(m0 - nm0);
        const float corr1 = __expf(m1 - nm1);
        m0 = nm0; m1 = nm1;

        float ps0 = 0.0f, ps1 = 0.0f;
        #pragma unroll
        for (int nt = 0; nt < 8; ++nt) {
            s[nt][0] = __expf(s[nt][0] - nm0);
            s[nt][1] = __expf(s[nt][1] - nm0);
            s[nt][2] = __expf(s[nt][2] - nm1);
            s[nt][3] = __expf(s[nt][3] - nm1);
            ps0 += s[nt][0] + s[nt][1];
            ps1 += s[nt][2] + s[nt][3];
        }
        ps0 += __shfl_xor_sync(0xffffffffu, ps0, 1);
        ps0 += __shfl_xor_sync(0xffffffffu, ps0, 2);
        ps1 += __shfl_xor_sync(0xffffffffu, ps1, 1);
        ps1 += __shfl_xor_sync(0xffffffffu, ps1, 2);
        l0 = l0 * corr0 + ps0;
        l1 = l1 * corr1 + ps1;

        #pragma unroll
        for (int nt = 0; nt < 8; ++nt) {
            o[nt][0] *= corr0; o[nt][1] *= corr0;
            o[nt][2] *= corr1; o[nt][3] *= corr1;
        }

        // ---- P -> per-warp smem (D-frag -> A-frag layout fix) ----
        #pragma unroll
        for (int nt = 0; nt < 8; ++nt) {
            *reinterpret_cast<float2*>(&sP[r * QSTR + nt * 8 + 2 * c]) =
                make_float2(s[nt][0], s[nt][1]);
            *reinterpret_cast<float2*>(&sP[(r + 8) * QSTR + nt * 8 + 2 * c]) =
                make_float2(s[nt][2], s[nt][3]);
        }
        __syncwarp();

        // ---- O += P V (tf32) ----
        #pragma unroll
        for (int kt = 0; kt < 8; ++kt) {
            uint32_t ap[4];
            ap[0] = f2tf32(sP[r * QSTR + kt * 8 + c]);
            ap[1] = f2tf32(sP[(r + 8) * QSTR + kt * 8 + c]);
            ap[2] = f2tf32(sP[r * QSTR + kt * 8 + c + 4]);
            ap[3] = f2tf32(sP[(r + 8) * QSTR + kt * 8 + c + 4]);
            #pragma unroll
            for (int nt = 0; nt < 8; ++nt) {
                uint32_t bv[2];
                bv[0] = f2tf32(bV[(kt * 8 + c) * QSTR + nt * 8 + r]);
                bv[1] = f2tf32(bV[(kt * 8 + c + 4) * QSTR + nt * 8 + r]);
                mma_tf32(o[nt], ap, bv);
            }
        }
        __syncwarp();
    }

    // ---- finalize + store ----
    const float inv0 = 1.0f / l0;
    const float inv1 = 1.0f / l1;
    const int row0 = s0 + wid * 16 + r;
    #pragma unroll
    for (int nt = 0; nt < 8; ++nt) {
        const int col = nh * HDd + nt * 8 + 2 * c;
        *reinterpret_cast<float2*>(&ctx[(size_t)(b * Ss + row0) * Hh + col]) =
            make_float2(o[nt][0] * inv0, o[nt][1] * inv0);
        *reinterpret_cast<float2*>(&ctx[(size_t)(b * Ss + row0 + 8) * Hh + col]) =
            make_float2(o[nt][2] * inv1, o[nt][3] * inv1);
    }
}

// ---------------------------------------------------------------------------
// Row LayerNorm over H=1024
// ---------------------------------------------------------------------------
__global__ __launch_bounds__(256) void ln_kernel(
    const float* __restrict__ X, const float* __restrict__ gamma,
    const float* __restrict__ beta, float* __restrict__ out)
{
    __shared__ float red[8];
    const int row = blockIdx.x;
    const int tid = threadIdx.x;

    const float4 v = reinterpret_cast<const float4*>(X + (size_t)row * Hh)[tid];
    float sum = v.x + v.y + v.z + v.w;
    #pragma unroll
    for (int o = 16; o; o >>= 1) sum += __shfl_xor_sync(0xffffffffu, sum, o);
    if ((tid & 31) == 0) red[tid >> 5] = sum;
    __syncthreads();
    float tot = 0.0f;
    #pragma unroll
    for (int i = 0; i < 8; ++i) tot += red[i];
    const float mu = tot * (1.0f / Hh);

    const float dx = v.x - mu, dy = v.y - mu, dz = v.z - mu, dw = v.w - mu;
    float sq = dx * dx + dy * dy + dz * dz + dw * dw;
    #pragma unroll
    for (int o = 16; o; o >>= 1) sq += __shfl_xor_sync(0xffffffffu, sq, o);
    __syncthreads();
    if ((tid & 31) == 0) red[tid >> 5] = sq;
    __syncthreads();
    float tot2 = 0.0f;
    #pragma unroll
    for (int i = 0; i < 8; ++i) tot2 += red[i];
    const float var = tot2 * (1.0f / Hh);
    const float rstd = rsqrtf(var + 1e-5f);

    const float4 gm = reinterpret_cast<const float4*>(gamma)[tid];
    const float4 bt = reinterpret_cast<const float4*>(beta)[tid];
    float4 o;
    o.x = dx * rstd * gm.x + bt.x;
    o.y = dy * rstd * gm.y + bt.y;
    o.z = dz * rstd * gm.z + bt.z;
    o.w = dw * rstd * gm.w + bt.w;
    reinterpret_cast<float4*>(out + (size_t)row * Hh)[tid] = o;
}

// ---------------------------------------------------------------------------
extern "C" void kernel_launch(void* const* d_in, const int* in_sizes, int n_in,
                              void* d_out, int out_size)
{
    const float* hs    = (const float*)d_in[0];
    const float* at    = (const float*)d_in[1];
    const int*   am    = (const int*)d_in[2];
    const float* Wq    = (const float*)d_in[3];
    const float* bq    = (const float*)d_in[4];
    const float* Wk    = (const float*)d_in[5];
    const float* bk    = (const float*)d_in[6];
    const float* Wv    = (const float*)d_in[7];
    const float* bv    = (const float*)d_in[8];
    const float* Wo    = (const float*)d_in[9];
    const float* bo    = (const float*)d_in[10];
    const float* gamma = (const float*)d_in[11];
    const float* beta  = (const float*)d_in[12];
    const float* rs    = (const float*)d_in[13];
    float* out = (float*)d_out;

    float *q, *k, *v, *ctx;
    cudaGetSymbolAddress((void**)&q,   g_q);
    cudaGetSymbolAddress((void**)&k,   g_k);
    cudaGetSymbolAddress((void**)&v,   g_v);
    cudaGetSymbolAddress((void**)&ctx, g_ctx);

    const dim3 blk(256);

    const int gemm_smem = 4 * STAGE_F * sizeof(float);
    // sQ/sP + 2x(K,V) + 2x64 mask ints
    const int attn_smem = (128 * QSTR + 4 * KVCH * QSTR) * sizeof(float)
                        + 2 * KVCH * sizeof(int);
    static int attr_done = 0;
    if (!attr_done) {
        cudaFuncSetAttribute(addmm_tf32, cudaFuncAttributeMaxDynamicSharedMemorySize, gemm_smem);
        cudaFuncSetAttribute(attn_mma, cudaFuncAttributeMaxDynamicSharedMemorySize, attn_smem);
        attr_done = 1;
    }

    // Projections
    addmm_tf32<<<dim3((Bb * Ss) / 128, Hh / 128), blk, gemm_smem>>>(hs, Wq, bq, nullptr, q);
    addmm_tf32<<<dim3((Bb * Aa) / 128, Hh / 128), blk, gemm_smem>>>(at, Wk, bk, nullptr, k);
    addmm_tf32<<<dim3((Bb * Aa) / 128, Hh / 128), blk, gemm_smem>>>(at, Wv, bv, nullptr, v);

    // Attention (tensor-core)
    attn_mma<<<dim3(Ss / 128, NHh, Bb), blk, attn_smem>>>(am, ctx);

    // Output projection (+bias, * clamp(rs,0,0.3)) into reused q buffer
    addmm_tf32<<<dim3((Bb * Ss) / 128, Hh / 128), blk, gemm_smem>>>(ctx, Wo, bo, rs, q);

    // LayerNorm -> final output
    ln_kernel<<<dim3(Bb * Ss), blk>>>(q, gamma, beta, out);
}

// round 4
// speedup vs baseline: 3.6239x; 1.0217x over previous
#include <cuda_runtime.h>
#include <math.h>
#include <stdint.h>

#define Bb 4
#define Ss 4096
#define Aa 512
#define Hh 1024
#define NHh 16
#define HDd 64

// Scratch (device globals: allocation-free rule)
__device__ float g_q[(size_t)Bb * Ss * Hh];    // q, later reused as delta
__device__ float g_k[(size_t)Bb * Aa * Hh];
__device__ float g_v[(size_t)Bb * Aa * Hh];
__device__ float g_ctx[(size_t)Bb * Ss * Hh];

// ---------------------------------------------------------------------------
// Helpers
// ---------------------------------------------------------------------------
__device__ __forceinline__ void cp_async16(uint32_t s, const void* g) {
    asm volatile("cp.async.cg.shared.global [%0], [%1], 16;" :: "r"(s), "l"(g));
}
__device__ __forceinline__ void cp_commit() {
    asm volatile("cp.async.commit_group;");
}
__device__ __forceinline__ void cp_wait0() {
    asm volatile("cp.async.wait_group 0;");
}
__device__ __forceinline__ void cp_wait1() {
    asm volatile("cp.async.wait_group 1;");
}
__device__ __forceinline__ uint32_t f2tf32(float f) {
    uint32_t u;
    asm("cvt.rna.tf32.f32 %0, %1;" : "=r"(u) : "f"(f));
    return u;
}
__device__ __forceinline__ void mma_tf32(float* d, const uint32_t* a, const uint32_t* b) {
    asm volatile(
        "mma.sync.aligned.m16n8k8.row.col.f32.tf32.tf32.f32 "
        "{%0,%1,%2,%3}, {%4,%5,%6,%7}, {%8,%9}, {%0,%1,%2,%3};"
        : "+f"(d[0]), "+f"(d[1]), "+f"(d[2]), "+f"(d[3])
        : "r"(a[0]), "r"(a[1]), "r"(a[2]), "r"(a[3]), "r"(b[0]), "r"(b[1]));
}

// ---------------------------------------------------------------------------
// addmm: C[M,1024] = A[M,1024] @ W[1024,1024]^T + bias (optional *clamp(rs))
// tf32 mma.sync, 128x128 tile, BK=32, 8 warps (64x32 warp tile), dbuf cp.async
// ---------------------------------------------------------------------------
#define KSTR 36
#define STAGE_F (128 * KSTR)

__global__ __launch_bounds__(256, 2) void addmm_tf32(
    const float* __restrict__ Ag, const float* __restrict__ Wg,
    const float* __restrict__ bias, const float* __restrict__ scale_ptr,
    float* __restrict__ C)
{
    extern __shared__ float smf[];
    const int K = 1024;
    const int tid  = threadIdx.x;
    const int lane = tid & 31;
    const int wid  = tid >> 5;
    const int wm   = wid & 1;
    const int wn   = wid >> 1;
    const int bm   = blockIdx.x * 128;
    const int bn   = blockIdx.y * 128;

    const int kv = tid & 7;
    const int rg = tid >> 3;

    const float* Aptr = Ag + (size_t)(bm + rg) * K + kv * 4;
    const float* Wptr = Wg + (size_t)(bn + rg) * K + kv * 4;

    const uint32_t sA = (uint32_t)__cvta_generic_to_shared(smf);
    const uint32_t sB = sA + 2u * STAGE_F * 4u;

    auto issue = [&](int kt, int buf) {
        const int kk = kt * 32;
        const uint32_t a_s = sA + (uint32_t)buf * STAGE_F * 4u;
        const uint32_t b_s = sB + (uint32_t)buf * STAGE_F * 4u;
        #pragma unroll
        for (int j = 0; j < 4; ++j) {
            const int row = rg + j * 32;
            cp_async16(a_s + (uint32_t)(row * KSTR + kv * 4) * 4u,
                       Aptr + (size_t)j * 32 * K + kk);
            cp_async16(b_s + (uint32_t)(row * KSTR + kv * 4) * 4u,
                       Wptr + (size_t)j * 32 * K + kk);
        }
    };

    float acc[4][4][4] = {};

    issue(0, 0);
    cp_commit();

    const int KT = K / 32;
    for (int kt = 0; kt < KT; ++kt) {
        cp_wait0();
        __syncthreads();
        if (kt + 1 < KT) {
            issue(kt + 1, (kt + 1) & 1);
            cp_commit();
        }
        const float* As = smf + (kt & 1) * STAGE_F;
        const float* Bs = smf + 2 * STAGE_F + (kt & 1) * STAGE_F;
        const int r = lane >> 2, c = lane & 3;

        #pragma unroll
        for (int ks = 0; ks < 4; ++ks) {
            uint32_t a[4][4], b[4][2];
            #pragma unroll
            for (int mt = 0; mt < 4; ++mt) {
                const float* base = As + (wm * 64 + mt * 16 + r) * KSTR + ks * 8 + c;
                a[mt][0] = f2tf32(base[0]);
                a[mt][1] = f2tf32(base[8 * KSTR]);
                a[mt][2] = f2tf32(base[4]);
                a[mt][3] = f2tf32(base[8 * KSTR + 4]);
            }
            #pragma unroll
            for (int nt = 0; nt < 4; ++nt) {
                const float* base = Bs + (wn * 32 + nt * 8 + r) * KSTR + ks * 8 + c;
                b[nt][0] = f2tf32(base[0]);
                b[nt][1] = f2tf32(base[4]);
            }
            #pragma unroll
            for (int mt = 0; mt < 4; ++mt)
                #pragma unroll
                for (int nt = 0; nt < 4; ++nt)
                    mma_tf32(acc[mt][nt], a[mt], b[nt]);
        }
        __syncthreads();
    }

    float scl = 1.0f;
    if (scale_ptr) scl = fminf(fmaxf(*scale_ptr, 0.0f), 0.3f);

    const int r = lane >> 2;
    const int c2 = (lane & 3) * 2;
    #pragma unroll
    for (int mt = 0; mt < 4; ++mt) {
        const int row0 = bm + wm * 64 + mt * 16 + r;
        #pragma unroll
        for (int nt = 0; nt < 4; ++nt) {
            const int col = bn + wn * 32 + nt * 8 + c2;
            const float b0 = bias[col], b1 = bias[col + 1];
            float2 v0 = make_float2((acc[mt][nt][0] + b0) * scl,
                                    (acc[mt][nt][1] + b1) * scl);
            float2 v1 = make_float2((acc[mt][nt][2] + b0) * scl,
                                    (acc[mt][nt][3] + b1) * scl);
            *reinterpret_cast<float2*>(&C[(size_t)row0 * 1024 + col]) = v0;
            *reinterpret_cast<float2*>(&C[(size_t)(row0 + 8) * 1024 + col]) = v1;
        }
    }
}

// ---------------------------------------------------------------------------
// Tensor-core flash attention.
// Block = 128 queries x 1 head: 8 warps, warp = 16 queries.
// K/V in 64-key chunks, double-buffered cp.async. After each chunk lands, a
// single block-wide pass converts K -> (hi,lo) tf32 and V -> tf32 in smem, so
// the mma loop issues pure LDS.u32 fragment loads (no per-warp cvt).
// QK^T in tf32x3 (fp32-grade scores), PV in tf32. P round-trips through
// per-warp smem to fix D-frag -> A-frag layout. Stride 68 -> conflict-free.
// ---------------------------------------------------------------------------
#define QSTR 68
#define KVCH 64
#define KVW (KVCH * QSTR)

__global__ __launch_bounds__(256) void attn_mma(
    const int* __restrict__ amask, float* __restrict__ ctx)
{
    extern __shared__ float sm[];
    float* sQ    = sm;                         // 128*68 (reused as sP)
    float* sKraw = sm + 128 * QSTR;            // 2 bufs; becomes Khi in place
    float* sKlo  = sKraw + 2 * KVW;            // 2 bufs
    float* sVraw = sKlo + 2 * KVW;             // 2 bufs; becomes Vt in place
    int*   sMi   = (int*)(sVraw + 2 * KVW);    // 2 * 64 ints

    const int s0  = blockIdx.x * 128;
    const int nh  = blockIdx.y;
    const int b   = blockIdx.z;
    const int tid = threadIdx.x;
    const int lane = tid & 31;
    const int wid  = tid >> 5;
    const int r = lane >> 2;
    const int c = lane & 3;

    const uint32_t sQa = (uint32_t)__cvta_generic_to_shared(sQ);
    const uint32_t sKa = (uint32_t)__cvta_generic_to_shared(sKraw);
    const uint32_t sVa = (uint32_t)__cvta_generic_to_shared(sVraw);
    const uint32_t sMa = (uint32_t)__cvta_generic_to_shared(sMi);

    // ---- issue Q tile load (group 0): 128 rows x 16 float4 ----
    #pragma unroll
    for (int i = 0; i < 8; ++i) {
        const int it = tid + i * 256;
        const int row = it >> 4, col = it & 15;
        cp_async16(sQa + (uint32_t)(row * QSTR + col * 4) * 4u,
                   &g_q[(size_t)(b * Ss + s0 + row) * Hh + nh * HDd + col * 4]);
    }
    cp_commit();

    auto load_kv = [&](int ch, int buf) {
        const int a0 = ch * KVCH;
        const uint32_t ko = sKa + (uint32_t)buf * KVW * 4u;
        const uint32_t vo = sVa + (uint32_t)buf * KVW * 4u;
        #pragma unroll
        for (int i = 0; i < 4; ++i) {
            const int it = tid + i * 256;
            const int row = it >> 4, col = it & 15;
            const size_t g = (size_t)(b * Aa + a0 + row) * Hh + nh * HDd + col * 4;
            cp_async16(ko + (uint32_t)(row * QSTR + col * 4) * 4u, &g_k[g]);
            cp_async16(vo + (uint32_t)(row * QSTR + col * 4) * 4u, &g_v[g]);
        }
        if (tid < 16)
            cp_async16(sMa + (uint32_t)buf * 256u + tid * 16u,
                       &amask[b * Aa + a0 + tid * 4]);
    };

    load_kv(0, 0);   // group 1
    cp_commit();

    cp_wait1();      // Q ready
    __syncthreads();

    // ---- build Q fragments (hi/lo split for tf32x3) ----
    uint32_t qh[8][4], ql[8][4];
    {
        const float* qb = sQ + (wid * 16) * QSTR;
        #pragma unroll
        for (int kt = 0; kt < 8; ++kt) {
            #pragma unroll
            for (int j = 0; j < 4; ++j) {
                const int rr = r + (j & 1) * 8;
                const int cc = kt * 8 + c + (j >> 1) * 4;
                const float f = qb[rr * QSTR + cc];
                const uint32_t hi = f2tf32(f);
                qh[kt][j] = hi;
                ql[kt][j] = f2tf32(f - __uint_as_float(hi));
            }
        }
    }
    __syncthreads();   // all warps done reading sQ; region becomes sP

    float m0 = -1e30f, m1 = -1e30f, l0 = 0.0f, l1 = 0.0f;
    float o[8][4] = {};
    float* sP = sQ + (wid * 16) * QSTR;   // per-warp private 16x68 region

    for (int ch = 0; ch < 8; ++ch) {
        const int buf = ch & 1;
        cp_wait0();
        __syncthreads();
        if (ch < 7) { load_kv(ch + 1, buf ^ 1); cp_commit(); }

        // ---- block-wide one-shot conversion: K -> hi/lo, V -> tf32 ----
        {
            float* Kr = sKraw + buf * KVW;
            uint32_t* Kh = (uint32_t*)Kr;
            uint32_t* Kl = (uint32_t*)(sKlo + buf * KVW);
            float* Vr = sVraw + buf * KVW;
            uint32_t* Vt = (uint32_t*)Vr;
            #pragma unroll
            for (int i = 0; i < 16; ++i) {
                const int idx = tid + i * 256;
                const int a = (idx >> 6) * QSTR + (idx & 63);
                const float f = Kr[a];
                const uint32_t hi = f2tf32(f);
                Kh[a] = hi;
                Kl[a] = f2tf32(f - __uint_as_float(hi));
                Vt[a] = f2tf32(Vr[a]);
            }
        }
        __syncthreads();

        const uint32_t* Kh = (const uint32_t*)(sKraw + buf * KVW);
        const uint32_t* Kl = (const uint32_t*)(sKlo  + buf * KVW);
        const uint32_t* Vt = (const uint32_t*)(sVraw + buf * KVW);
        const int* bM = sMi + buf * KVCH;

        // ---- S = Q K^T (tf32x3, pure LDS fragments) ----
        float s[8][4] = {};
        #pragma unroll
        for (int kt = 0; kt < 8; ++kt) {
            #pragma unroll
            for (int nt = 0; nt < 8; ++nt) {
                const int base = (nt * 8 + r) * QSTR + kt * 8 + c;
                uint32_t bh[2] = { Kh[base], Kh[base + 4] };
                uint32_t bl[2] = { Kl[base], Kl[base + 4] };
                mma_tf32(s[nt], qh[kt], bh);
                mma_tf32(s[nt], qh[kt], bl);
                mma_tf32(s[nt], ql[kt], bh);
            }
        }

        // ---- scale + clip + mask, row maxima ----
        float rm0 = -1e30f, rm1 = -1e30f;
        #pragma unroll
        for (int nt = 0; nt < 8; ++nt) {
            const int mk0 = bM[nt * 8 + 2 * c];
            const int mk1 = bM[nt * 8 + 2 * c + 1];
            #pragma unroll
            for (int j = 0; j < 4; ++j) {
                float sc = fminf(fmaxf(s[nt][j] * 0.125f, -50.0f), 50.0f);
                const int mk = (j & 1) ? mk1 : mk0;
                if (mk <= 0) sc = -50.0f;
                s[nt][j] = sc;
            }
            rm0 = fmaxf(rm0, fmaxf(s[nt][0], s[nt][1]));
            rm1 = fmaxf(rm1, fmaxf(s[nt][2], s[nt][3]));
        }
        rm0 = fmaxf(rm0, __shfl_xor_sync(0xffffffffu, rm0, 1));
        rm0 = fmaxf(rm0, __shfl_xor_sync(0xffffffffu, rm0, 2));
        rm1 = fmaxf(rm1, __shfl_xor_sync(0xffffffffu, rm1, 1));
        rm1 = fmaxf(rm1, __shfl_xor_sync(0xffffffffu, rm1, 2));

        const float nm0 = fmaxf(m0, rm0);
        const float nm1 = fmaxf(m1, rm1);
        const float corr0 = __expf(m0 - nm0);
        const float corr1 = __expf(m1 - nm1);
        m0 = nm0; m1 = nm1;

        float ps0 = 0.0f, ps1 = 0.0f;
        #pragma unroll
        for (int nt = 0; nt < 8; ++nt) {
            s[nt][0] = __expf(s[nt][0] - nm0);
            s[nt][1] = __expf(s[nt][1] - nm0);
            s[nt][2] = __expf(s[nt][2] - nm1);
            s[nt][3] = __expf(s[nt][3] - nm1);
            ps0 += s[nt][0] + s[nt][1];
            ps1 += s[nt][2] + s[nt][3];
        }
        ps0 += __shfl_xor_sync(0xffffffffu, ps0, 1);
        ps0 += __shfl_xor_sync(0xffffffffu, ps0, 2);
        ps1 += __shfl_xor_sync(0xffffffffu, ps1, 1);
        ps1 += __shfl_xor_sync(0xffffffffu, ps1, 2);
        l0 = l0 * corr0 + ps0;
        l1 = l1 * corr1 + ps1;

        #pragma unroll
        for (int nt = 0; nt < 8; ++nt) {
            o[nt][0] *= corr0; o[nt][1] *= corr0;
            o[nt][2] *= corr1; o[nt][3] *= corr1;
        }

        // ---- P -> per-warp smem (D-frag -> A-frag layout fix) ----
        #pragma unroll
        for (int nt = 0; nt < 8; ++nt) {
            *reinterpret_cast<float2*>(&sP[r * QSTR + nt * 8 + 2 * c]) =
                make_float2(s[nt][0], s[nt][1]);
            *reinterpret_cast<float2*>(&sP[(r + 8) * QSTR + nt * 8 + 2 * c]) =
                make_float2(s[nt][2], s[nt][3]);
        }
        __syncwarp();

        // ---- O += P V (tf32) ----
        #pragma unroll
        for (int kt = 0; kt < 8; ++kt) {
            uint32_t ap[4];
            ap[0] = f2tf32(sP[r * QSTR + kt * 8 + c]);
            ap[1] = f2tf32(sP[(r + 8) * QSTR + kt * 8 + c]);
            ap[2] = f2tf32(sP[r * QSTR + kt * 8 + c + 4]);
            ap[3] = f2tf32(sP[(r + 8) * QSTR + kt * 8 + c + 4]);
            #pragma unroll
            for (int nt = 0; nt < 8; ++nt) {
                uint32_t bv[2];
                bv[0] = Vt[(kt * 8 + c) * QSTR + nt * 8 + r];
                bv[1] = Vt[(kt * 8 + c + 4) * QSTR + nt * 8 + r];
                mma_tf32(o[nt], ap, bv);
            }
        }
        __syncwarp();
    }

    // ---- finalize + store ----
    const float inv0 = 1.0f / l0;
    const float inv1 = 1.0f / l1;
    const int row0 = s0 + wid * 16 + r;
    #pragma unroll
    for (int nt = 0; nt < 8; ++nt) {
        const int col = nh * HDd + nt * 8 + 2 * c;
        *reinterpret_cast<float2*>(&ctx[(size_t)(b * Ss + row0) * Hh + col]) =
            make_float2(o[nt][0] * inv0, o[nt][1] * inv0);
        *reinterpret_cast<float2*>(&ctx[(size_t)(b * Ss + row0 + 8) * Hh + col]) =
            make_float2(o[nt][2] * inv1, o[nt][3] * inv1);
    }
}

// ---------------------------------------------------------------------------
// Row LayerNorm over H=1024
// ---------------------------------------------------------------------------
__global__ __launch_bounds__(256) void ln_kernel(
    const float* __restrict__ X, const float* __restrict__ gamma,
    const float* __restrict__ beta, float* __restrict__ out)
{
    __shared__ float red[8];
    const int row = blockIdx.x;
    const int tid = threadIdx.x;

    const float4 v = reinterpret_cast<const float4*>(X + (size_t)row * Hh)[tid];
    float sum = v.x + v.y + v.z + v.w;
    #pragma unroll
    for (int o = 16; o; o >>= 1) sum += __shfl_xor_sync(0xffffffffu, sum, o);
    if ((tid & 31) == 0) red[tid >> 5] = sum;
    __syncthreads();
    float tot = 0.0f;
    #pragma unroll
    for (int i = 0; i < 8; ++i) tot += red[i];
    const float mu = tot * (1.0f / Hh);

    const float dx = v.x - mu, dy = v.y - mu, dz = v.z - mu, dw = v.w - mu;
    float sq = dx * dx + dy * dy + dz * dz + dw * dw;
    #pragma unroll
    for (int o = 16; o; o >>= 1) sq += __shfl_xor_sync(0xffffffffu, sq, o);
    __syncthreads();
    if ((tid & 31) == 0) red[tid >> 5] = sq;
    __syncthreads();
    float tot2 = 0.0f;
    #pragma unroll
    for (int i = 0; i < 8; ++i) tot2 += red[i];
    const float var = tot2 * (1.0f / Hh);
    const float rstd = rsqrtf(var + 1e-5f);

    const float4 gm = reinterpret_cast<const float4*>(gamma)[tid];
    const float4 bt = reinterpret_cast<const float4*>(beta)[tid];
    float4 o;
    o.x = dx * rstd * gm.x + bt.x;
    o.y = dy * rstd * gm.y + bt.y;
    o.z = dz * rstd * gm.z + bt.z;
    o.w = dw * rstd * gm.w + bt.w;
    reinterpret_cast<float4*>(out + (size_t)row * Hh)[tid] = o;
}

// ---------------------------------------------------------------------------
extern "C" void kernel_launch(void* const* d_in, const int* in_sizes, int n_in,
                              void* d_out, int out_size)
{
    const float* hs    = (const float*)d_in[0];
    const float* at    = (const float*)d_in[1];
    const int*   am    = (const int*)d_in[2];
    const float* Wq    = (const float*)d_in[3];
    const float* bq    = (const float*)d_in[4];
    const float* Wk    = (const float*)d_in[5];
    const float* bk    = (const float*)d_in[6];
    const float* Wv    = (const float*)d_in[7];
    const float* bv    = (const float*)d_in[8];
    const float* Wo    = (const float*)d_in[9];
    const float* bo    = (const float*)d_in[10];
    const float* gamma = (const float*)d_in[11];
    const float* beta  = (const float*)d_in[12];
    const float* rs    = (const float*)d_in[13];
    float* out = (float*)d_out;

    float *q, *k, *v, *ctx;
    cudaGetSymbolAddress((void**)&q,   g_q);
    cudaGetSymbolAddress((void**)&k,   g_k);
    cudaGetSymbolAddress((void**)&v,   g_v);
    cudaGetSymbolAddress((void**)&ctx, g_ctx);

    const dim3 blk(256);

    const int gemm_smem = 4 * STAGE_F * sizeof(float);
    // sQ/sP + 2 bufs x (Khi, Klo, Vt) + 2x64 mask ints
    const int attn_smem = (128 * QSTR + 6 * KVW) * sizeof(float)
                        + 2 * KVCH * sizeof(int);
    static int attr_done = 0;
    if (!attr_done) {
        cudaFuncSetAttribute(addmm_tf32, cudaFuncAttributeMaxDynamicSharedMemorySize, gemm_smem);
        cudaFuncSetAttribute(attn_mma, cudaFuncAttributeMaxDynamicSharedMemorySize, attn_smem);
        attr_done = 1;
    }

    // Projections
    addmm_tf32<<<dim3((Bb * Ss) / 128, Hh / 128), blk, gemm_smem>>>(hs, Wq, bq, nullptr, q);
    addmm_tf32<<<dim3((Bb * Aa) / 128, Hh / 128), blk, gemm_smem>>>(at, Wk, bk, nullptr, k);
    addmm_tf32<<<dim3((Bb * Aa) / 128, Hh / 128), blk, gemm_smem>>>(at, Wv, bv, nullptr, v);

    // Attention (tensor-core)
    attn_mma<<<dim3(Ss / 128, NHh, Bb), blk, attn_smem>>>(am, ctx);

    // Output projection (+bias, * clamp(rs,0,0.3)) into reused q buffer
    addmm_tf32<<<dim3((Bb * Ss) / 128, Hh / 128), blk, gemm_smem>>>(ctx, Wo, bo, rs, q);

    // LayerNorm -> final output
    ln_kernel<<<dim3(Bb * Ss), blk>>>(q, gamma, beta, out);
}

// round 5
// speedup vs baseline: 3.9033x; 1.0771x over previous
#include <cuda_runtime.h>
#include <math.h>
#include <stdint.h>

#define Bb 4
#define Ss 4096
#define Aa 512
#define Hh 1024
#define NHh 16
#define HDd 64

// Scratch (device globals: allocation-free rule)
__device__ float g_q[(size_t)Bb * Ss * Hh];    // q, later reused as delta
__device__ float g_k[(size_t)Bb * Aa * Hh];
__device__ float g_v[(size_t)Bb * Aa * Hh];
__device__ float g_ctx[(size_t)Bb * Ss * Hh];

// ---------------------------------------------------------------------------
// Helpers
// ---------------------------------------------------------------------------
__device__ __forceinline__ void cp_async16(uint32_t s, const void* g) {
    asm volatile("cp.async.cg.shared.global [%0], [%1], 16;" :: "r"(s), "l"(g));
}
__device__ __forceinline__ void cp_commit() {
    asm volatile("cp.async.commit_group;");
}
__device__ __forceinline__ void cp_wait0() {
    asm volatile("cp.async.wait_group 0;");
}
__device__ __forceinline__ void cp_wait1() {
    asm volatile("cp.async.wait_group 1;");
}
__device__ __forceinline__ uint32_t f2tf32(float f) {
    uint32_t u;
    asm("cvt.rna.tf32.f32 %0, %1;" : "=r"(u) : "f"(f));
    return u;
}
__device__ __forceinline__ void mma_tf32(float* d, const uint32_t* a, const uint32_t* b) {
    asm volatile(
        "mma.sync.aligned.m16n8k8.row.col.f32.tf32.tf32.f32 "
        "{%0,%1,%2,%3}, {%4,%5,%6,%7}, {%8,%9}, {%0,%1,%2,%3};"
        : "+f"(d[0]), "+f"(d[1]), "+f"(d[2]), "+f"(d[3])
        : "r"(a[0]), "r"(a[1]), "r"(a[2]), "r"(a[3]), "r"(b[0]), "r"(b[1]));
}

// ---------------------------------------------------------------------------
// addmm: C[M,1024] = A[M,1024] @ W[1024,1024]^T + bias (optional *clamp(rs))
// tf32 mma.sync, 128x128 tile, BK=32, 8 warps (64x32 warp tile), dbuf cp.async
// ---------------------------------------------------------------------------
#define KSTR 36
#define STAGE_F (128 * KSTR)

__global__ __launch_bounds__(256, 2) void addmm_tf32(
    const float* __restrict__ Ag, const float* __restrict__ Wg,
    const float* __restrict__ bias, const float* __restrict__ scale_ptr,
    float* __restrict__ C)
{
    extern __shared__ float smf[];
    const int K = 1024;
    const int tid  = threadIdx.x;
    const int lane = tid & 31;
    const int wid  = tid >> 5;
    const int wm   = wid & 1;
    const int wn   = wid >> 1;
    const int bm   = blockIdx.x * 128;
    const int bn   = blockIdx.y * 128;

    const int kv = tid & 7;
    const int rg = tid >> 3;

    const float* Aptr = Ag + (size_t)(bm + rg) * K + kv * 4;
    const float* Wptr = Wg + (size_t)(bn + rg) * K + kv * 4;

    const uint32_t sA = (uint32_t)__cvta_generic_to_shared(smf);
    const uint32_t sB = sA + 2u * STAGE_F * 4u;

    auto issue = [&](int kt, int buf) {
        const int kk = kt * 32;
        const uint32_t a_s = sA + (uint32_t)buf * STAGE_F * 4u;
        const uint32_t b_s = sB + (uint32_t)buf * STAGE_F * 4u;
        #pragma unroll
        for (int j = 0; j < 4; ++j) {
            const int row = rg + j * 32;
            cp_async16(a_s + (uint32_t)(row * KSTR + kv * 4) * 4u,
                       Aptr + (size_t)j * 32 * K + kk);
            cp_async16(b_s + (uint32_t)(row * KSTR + kv * 4) * 4u,
                       Wptr + (size_t)j * 32 * K + kk);
        }
    };

    float acc[4][4][4] = {};

    issue(0, 0);
    cp_commit();

    const int KT = K / 32;
    for (int kt = 0; kt < KT; ++kt) {
        cp_wait0();
        __syncthreads();
        if (kt + 1 < KT) {
            issue(kt + 1, (kt + 1) & 1);
            cp_commit();
        }
        const float* As = smf + (kt & 1) * STAGE_F;
        const float* Bs = smf + 2 * STAGE_F + (kt & 1) * STAGE_F;
        const int r = lane >> 2, c = lane & 3;

        #pragma unroll
        for (int ks = 0; ks < 4; ++ks) {
            uint32_t a[4][4], b[4][2];
            #pragma unroll
            for (int mt = 0; mt < 4; ++mt) {
                const float* base = As + (wm * 64 + mt * 16 + r) * KSTR + ks * 8 + c;
                a[mt][0] = f2tf32(base[0]);
                a[mt][1] = f2tf32(base[8 * KSTR]);
                a[mt][2] = f2tf32(base[4]);
                a[mt][3] = f2tf32(base[8 * KSTR + 4]);
            }
            #pragma unroll
            for (int nt = 0; nt < 4; ++nt) {
                const float* base = Bs + (wn * 32 + nt * 8 + r) * KSTR + ks * 8 + c;
                b[nt][0] = f2tf32(base[0]);
                b[nt][1] = f2tf32(base[4]);
            }
            #pragma unroll
            for (int mt = 0; mt < 4; ++mt)
                #pragma unroll
                for (int nt = 0; nt < 4; ++nt)
                    mma_tf32(acc[mt][nt], a[mt], b[nt]);
        }
        __syncthreads();
    }

    float scl = 1.0f;
    if (scale_ptr) scl = fminf(fmaxf(*scale_ptr, 0.0f), 0.3f);

    const int r = lane >> 2;
    const int c2 = (lane & 3) * 2;
    #pragma unroll
    for (int mt = 0; mt < 4; ++mt) {
        const int row0 = bm + wm * 64 + mt * 16 + r;
        #pragma unroll
        for (int nt = 0; nt < 4; ++nt) {
            const int col = bn + wn * 32 + nt * 8 + c2;
            const float b0 = bias[col], b1 = bias[col + 1];
            float2 v0 = make_float2((acc[mt][nt][0] + b0) * scl,
                                    (acc[mt][nt][1] + b1) * scl);
            float2 v1 = make_float2((acc[mt][nt][2] + b0) * scl,
                                    (acc[mt][nt][3] + b1) * scl);
            *reinterpret_cast<float2*>(&C[(size_t)row0 * 1024 + col]) = v0;
            *reinterpret_cast<float2*>(&C[(size_t)(row0 + 8) * 1024 + col]) = v1;
        }
    }
}

// ---------------------------------------------------------------------------
// Tensor-core flash attention.
// Block = 128 queries x 1 head: 8 warps, warp = 16 queries.
// K/V in 64-key chunks, double-buffered cp.async. After each chunk lands, one
// block-wide float4 pass converts K and V to tf32 in place (rna). QK^T uses
// tf32x2 (qh*kh + ql*kh; Q hi/lo lives in registers), PV plain tf32.
// P round-trips through per-warp smem to fix D-frag -> A-frag layout.
// Stride 68 -> conflict-free fragment LDS.
// ---------------------------------------------------------------------------
#define QSTR 68
#define KVCH 64
#define KVW (KVCH * QSTR)

__global__ __launch_bounds__(256) void attn_mma(
    const int* __restrict__ amask, float* __restrict__ ctx)
{
    extern __shared__ float sm[];
    float* sQ    = sm;                         // 128*68 (reused as sP)
    float* sKraw = sm + 128 * QSTR;            // 2 bufs; becomes Khi in place
    float* sVraw = sKraw + 2 * KVW;            // 2 bufs; becomes Vt in place
    int*   sMi   = (int*)(sVraw + 2 * KVW);    // 2 * 64 ints

    const int s0  = blockIdx.x * 128;
    const int nh  = blockIdx.y;
    const int b   = blockIdx.z;
    const int tid = threadIdx.x;
    const int lane = tid & 31;
    const int wid  = tid >> 5;
    const int r = lane >> 2;
    const int c = lane & 3;

    const uint32_t sQa = (uint32_t)__cvta_generic_to_shared(sQ);
    const uint32_t sKa = (uint32_t)__cvta_generic_to_shared(sKraw);
    const uint32_t sVa = (uint32_t)__cvta_generic_to_shared(sVraw);
    const uint32_t sMa = (uint32_t)__cvta_generic_to_shared(sMi);

    // ---- issue Q tile load (group 0): 128 rows x 16 float4 ----
    #pragma unroll
    for (int i = 0; i < 8; ++i) {
        const int it = tid + i * 256;
        const int row = it >> 4, col = it & 15;
        cp_async16(sQa + (uint32_t)(row * QSTR + col * 4) * 4u,
                   &g_q[(size_t)(b * Ss + s0 + row) * Hh + nh * HDd + col * 4]);
    }
    cp_commit();

    auto load_kv = [&](int ch, int buf) {
        const int a0 = ch * KVCH;
        const uint32_t ko = sKa + (uint32_t)buf * KVW * 4u;
        const uint32_t vo = sVa + (uint32_t)buf * KVW * 4u;
        #pragma unroll
        for (int i = 0; i < 4; ++i) {
            const int it = tid + i * 256;
            const int row = it >> 4, col = it & 15;
            const size_t g = (size_t)(b * Aa + a0 + row) * Hh + nh * HDd + col * 4;
            cp_async16(ko + (uint32_t)(row * QSTR + col * 4) * 4u, &g_k[g]);
            cp_async16(vo + (uint32_t)(row * QSTR + col * 4) * 4u, &g_v[g]);
        }
        if (tid < 16)
            cp_async16(sMa + (uint32_t)buf * 256u + tid * 16u,
                       &amask[b * Aa + a0 + tid * 4]);
    };

    load_kv(0, 0);   // group 1
    cp_commit();

    cp_wait1();      // Q ready
    __syncthreads();

    // ---- build Q fragments (hi/lo split; lo correction stays in regs) ----
    uint32_t qh[8][4], ql[8][4];
    {
        const float* qb = sQ + (wid * 16) * QSTR;
        #pragma unroll
        for (int kt = 0; kt < 8; ++kt) {
            #pragma unroll
            for (int j = 0; j < 4; ++j) {
                const int rr = r + (j & 1) * 8;
                const int cc = kt * 8 + c + (j >> 1) * 4;
                const float f = qb[rr * QSTR + cc];
                const uint32_t hi = f2tf32(f);
                qh[kt][j] = hi;
                ql[kt][j] = f2tf32(f - __uint_as_float(hi));
            }
        }
    }
    __syncthreads();   // all warps done reading sQ; region becomes sP

    float m0 = -1e30f, m1 = -1e30f, l0 = 0.0f, l1 = 0.0f;
    float o[8][4] = {};
    float* sP = sQ + (wid * 16) * QSTR;   // per-warp private 16x68 region

    for (int ch = 0; ch < 8; ++ch) {
        const int buf = ch & 1;
        cp_wait0();
        __syncthreads();
        if (ch < 7) { load_kv(ch + 1, buf ^ 1); cp_commit(); }

        // ---- block-wide float4 conversion: K,V -> tf32 (rna) in place ----
        {
            float4* K4 = (float4*)(sKraw + buf * KVW);
            float4* V4 = (float4*)(sVraw + buf * KVW);
            #pragma unroll
            for (int i = 0; i < 4; ++i) {
                const int idx4 = tid + i * 256;
                const int a = ((idx4 >> 4) * QSTR) / 4 + (idx4 & 15);
                float4 kf = K4[a];
                kf.x = __uint_as_float(f2tf32(kf.x));
                kf.y = __uint_as_float(f2tf32(kf.y));
                kf.z = __uint_as_float(f2tf32(kf.z));
                kf.w = __uint_as_float(f2tf32(kf.w));
                K4[a] = kf;
                float4 vf = V4[a];
                vf.x = __uint_as_float(f2tf32(vf.x));
                vf.y = __uint_as_float(f2tf32(vf.y));
                vf.z = __uint_as_float(f2tf32(vf.z));
                vf.w = __uint_as_float(f2tf32(vf.w));
                V4[a] = vf;
            }
        }
        __syncthreads();

        const uint32_t* Kh = (const uint32_t*)(sKraw + buf * KVW);
        const uint32_t* Vt = (const uint32_t*)(sVraw + buf * KVW);
        const int* bM = sMi + buf * KVCH;

        // ---- S = Q K^T (tf32x2: qh*kh + ql*kh) ----
        float s[8][4] = {};
        #pragma unroll
        for (int kt = 0; kt < 8; ++kt) {
            #pragma unroll
            for (int nt = 0; nt < 8; ++nt) {
                const int base = (nt * 8 + r) * QSTR + kt * 8 + c;
                uint32_t bh[2] = { Kh[base], Kh[base + 4] };
                mma_tf32(s[nt], qh[kt], bh);
                mma_tf32(s[nt], ql[kt], bh);
            }
        }

        // ---- scale + clip + mask, row maxima ----
        float rm0 = -1e30f, rm1 = -1e30f;
        #pragma unroll
        for (int nt = 0; nt < 8; ++nt) {
            const int mk0 = bM[nt * 8 + 2 * c];
            const int mk1 = bM[nt * 8 + 2 * c + 1];
            #pragma unroll
            for (int j = 0; j < 4; ++j) {
                float sc = fminf(fmaxf(s[nt][j] * 0.125f, -50.0f), 50.0f);
                const int mk = (j & 1) ? mk1 : mk0;
                if (mk <= 0) sc = -50.0f;
                s[nt][j] = sc;
            }
            rm0 = fmaxf(rm0, fmaxf(s[nt][0], s[nt][1]));
            rm1 = fmaxf(rm1, fmaxf(s[nt][2], s[nt][3]));
        }
        rm0 = fmaxf(rm0, __shfl_xor_sync(0xffffffffu, rm0, 1));
        rm0 = fmaxf(rm0, __shfl_xor_sync(0xffffffffu, rm0, 2));
        rm1 = fmaxf(rm1, __shfl_xor_sync(0xffffffffu, rm1, 1));
        rm1 = fmaxf(rm1, __shfl_xor_sync(0xffffffffu, rm1, 2));

        const float nm0 = fmaxf(m0, rm0);
        const float nm1 = fmaxf(m1, rm1);
        const float corr0 = __expf(m0 - nm0);
        const float corr1 = __expf(m1 - nm1);
        m0 = nm0; m1 = nm1;

        float ps0 = 0.0f, ps1 = 0.0f;
        #pragma unroll
        for (int nt = 0; nt < 8; ++nt) {
            s[nt][0] = __expf(s[nt][0] - nm0);
            s[nt][1] = __expf(s[nt][1] - nm0);
            s[nt][2] = __expf(s[nt][2] - nm1);
            s[nt][3] = __expf(s[nt][3] - nm1);
            ps0 += s[nt][0] + s[nt][1];
            ps1 += s[nt][2] + s[nt][3];
        }
        ps0 += __shfl_xor_sync(0xffffffffu, ps0, 1);
        ps0 += __shfl_xor_sync(0xffffffffu, ps0, 2);
        ps1 += __shfl_xor_sync(0xffffffffu, ps1, 1);
        ps1 += __shfl_xor_sync(0xffffffffu, ps1, 2);
        l0 = l0 * corr0 + ps0;
        l1 = l1 * corr1 + ps1;

        #pragma unroll
        for (int nt = 0; nt < 8; ++nt) {
            o[nt][0] *= corr0; o[nt][1] *= corr0;
            o[nt][2] *= corr1; o[nt][3] *= corr1;
        }

        // ---- P -> per-warp smem (D-frag -> A-frag layout fix) ----
        #pragma unroll
        for (int nt = 0; nt < 8; ++nt) {
            *reinterpret_cast<float2*>(&sP[r * QSTR + nt * 8 + 2 * c]) =
                make_float2(s[nt][0], s[nt][1]);
            *reinterpret_cast<float2*>(&sP[(r + 8) * QSTR + nt * 8 + 2 * c]) =
                make_float2(s[nt][2], s[nt][3]);
        }
        __syncwarp();

        // ---- O += P V (tf32) ----
        #pragma unroll
        for (int kt = 0; kt < 8; ++kt) {
            uint32_t ap[4];
            ap[0] = f2tf32(sP[r * QSTR + kt * 8 + c]);
            ap[1] = f2tf32(sP[(r + 8) * QSTR + kt * 8 + c]);
            ap[2] = f2tf32(sP[r * QSTR + kt * 8 + c + 4]);
            ap[3] = f2tf32(sP[(r + 8) * QSTR + kt * 8 + c + 4]);
            #pragma unroll
            for (int nt = 0; nt < 8; ++nt) {
                uint32_t bv[2];
                bv[0] = Vt[(kt * 8 + c) * QSTR + nt * 8 + r];
                bv[1] = Vt[(kt * 8 + c + 4) * QSTR + nt * 8 + r];
                mma_tf32(o[nt], ap, bv);
            }
        }
        __syncwarp();
    }

    // ---- finalize + store ----
    const float inv0 = 1.0f / l0;
    const float inv1 = 1.0f / l1;
    const int row0 = s0 + wid * 16 + r;
    #pragma unroll
    for (int nt = 0; nt < 8; ++nt) {
        const int col = nh * HDd + nt * 8 + 2 * c;
        *reinterpret_cast<float2*>(&ctx[(size_t)(b * Ss + row0) * Hh + col]) =
            make_float2(o[nt][0] * inv0, o[nt][1] * inv0);
        *reinterpret_cast<float2*>(&ctx[(size_t)(b * Ss + row0 + 8) * Hh + col]) =
            make_float2(o[nt][2] * inv1, o[nt][3] * inv1);
    }
}

// ---------------------------------------------------------------------------
// Row LayerNorm over H=1024
// ---------------------------------------------------------------------------
__global__ __launch_bounds__(256) void ln_kernel(
    const float* __restrict__ X, const float* __restrict__ gamma,
    const float* __restrict__ beta, float* __restrict__ out)
{
    __shared__ float red[8];
    const int row = blockIdx.x;
    const int tid = threadIdx.x;

    const float4 v = reinterpret_cast<const float4*>(X + (size_t)row * Hh)[tid];
    float sum = v.x + v.y + v.z + v.w;
    #pragma unroll
    for (int o = 16; o; o >>= 1) sum += __shfl_xor_sync(0xffffffffu, sum, o);
    if ((tid & 31) == 0) red[tid >> 5] = sum;
    __syncthreads();
    float tot = 0.0f;
    #pragma unroll
    for (int i = 0; i < 8; ++i) tot += red[i];
    const float mu = tot * (1.0f / Hh);

    const float dx = v.x - mu, dy = v.y - mu, dz = v.z - mu, dw = v.w - mu;
    float sq = dx * dx + dy * dy + dz * dz + dw * dw;
    #pragma unroll
    for (int o = 16; o; o >>= 1) sq += __shfl_xor_sync(0xffffffffu, sq, o);
    __syncthreads();
    if ((tid & 31) == 0) red[tid >> 5] = sq;
    __syncthreads();
    float tot2 = 0.0f;
    #pragma unroll
    for (int i = 0; i < 8; ++i) tot2 += red[i];
    const float var = tot2 * (1.0f / Hh);
    const float rstd = rsqrtf(var + 1e-5f);

    const float4 gm = reinterpret_cast<const float4*>(gamma)[tid];
    const float4 bt = reinterpret_cast<const float4*>(beta)[tid];
    float4 o;
    o.x = dx * rstd * gm.x + bt.x;
    o.y = dy * rstd * gm.y + bt.y;
    o.z = dz * rstd * gm.z + bt.z;
    o.w = dw * rstd * gm.w + bt.w;
    reinterpret_cast<float4*>(out + (size_t)row * Hh)[tid] = o;
}

// ---------------------------------------------------------------------------
extern "C" void kernel_launch(void* const* d_in, const int* in_sizes, int n_in,
                              void* d_out, int out_size)
{
    const float* hs    = (const float*)d_in[0];
    const float* at    = (const float*)d_in[1];
    const int*   am    = (const int*)d_in[2];
    const float* Wq    = (const float*)d_in[3];
    const float* bq    = (const float*)d_in[4];
    const float* Wk    = (const float*)d_in[5];
    const float* bk    = (const float*)d_in[6];
    const float* Wv    = (const float*)d_in[7];
    const float* bv    = (const float*)d_in[8];
    const float* Wo    = (const float*)d_in[9];
    const float* bo    = (const float*)d_in[10];
    const float* gamma = (const float*)d_in[11];
    const float* beta  = (const float*)d_in[12];
    const float* rs    = (const float*)d_in[13];
    float* out = (float*)d_out;

    float *q, *k, *v, *ctx;
    cudaGetSymbolAddress((void**)&q,   g_q);
    cudaGetSymbolAddress((void**)&k,   g_k);
    cudaGetSymbolAddress((void**)&v,   g_v);
    cudaGetSymbolAddress((void**)&ctx, g_ctx);

    const dim3 blk(256);

    const int gemm_smem = 4 * STAGE_F * sizeof(float);
    // sQ/sP + 2 bufs x (Khi, Vt) + 2x64 mask ints
    const int attn_smem = (128 * QSTR + 4 * KVW) * sizeof(float)
                        + 2 * KVCH * sizeof(int);
    static int attr_done = 0;
    if (!attr_done) {
        cudaFuncSetAttribute(addmm_tf32, cudaFuncAttributeMaxDynamicSharedMemorySize, gemm_smem);
        cudaFuncSetAttribute(attn_mma, cudaFuncAttributeMaxDynamicSharedMemorySize, attn_smem);
        attr_done = 1;
    }

    // Projections
    addmm_tf32<<<dim3((Bb * Ss) / 128, Hh / 128), blk, gemm_smem>>>(hs, Wq, bq, nullptr, q);
    addmm_tf32<<<dim3((Bb * Aa) / 128, Hh / 128), blk, gemm_smem>>>(at, Wk, bk, nullptr, k);
    addmm_tf32<<<dim3((Bb * Aa) / 128, Hh / 128), blk, gemm_smem>>>(at, Wv, bv, nullptr, v);

    // Attention (tensor-core)
    attn_mma<<<dim3(Ss / 128, NHh, Bb), blk, attn_smem>>>(am, ctx);

    // Output projection (+bias, * clamp(rs,0,0.3)) into reused q buffer
    addmm_tf32<<<dim3((Bb * Ss) / 128, Hh / 128), blk, gemm_smem>>>(ctx, Wo, bo, rs, q);

    // LayerNorm -> final output
    ln_kernel<<<dim3(Bb * Ss), blk>>>(q, gamma, beta, out);
}

// round 6
// speedup vs baseline: 4.1567x; 1.0649x over previous
#include <cuda_runtime.h>
#include <math.h>
#include <stdint.h>

#define Bb 4
#define Ss 4096
#define Aa 512
#define Hh 1024
#define NHh 16
#define HDd 64

// Scratch (device globals: allocation-free rule)
__device__ float g_q[(size_t)Bb * Ss * Hh];    // q (fp32), later reused as delta
__device__ float g_k[(size_t)Bb * Aa * Hh];    // tf32-rounded
__device__ float g_v[(size_t)Bb * Aa * Hh];    // tf32-rounded
__device__ float g_ctx[(size_t)Bb * Ss * Hh];  // tf32-rounded
__device__ float g_hsr[(size_t)Bb * Ss * Hh];  // tf32-rounded hidden_states
__device__ float g_atr[(size_t)Bb * Aa * Hh];  // tf32-rounded audio_tokens
__device__ float g_wr[(size_t)4 * Hh * Hh];    // tf32-rounded Wq,Wk,Wv,Wo

// ---------------------------------------------------------------------------
// Helpers
// ---------------------------------------------------------------------------
__device__ __forceinline__ void cp_async16(uint32_t s, const void* g) {
    asm volatile("cp.async.cg.shared.global [%0], [%1], 16;" :: "r"(s), "l"(g));
}
__device__ __forceinline__ void cp_commit() {
    asm volatile("cp.async.commit_group;");
}
__device__ __forceinline__ void cp_wait0() {
    asm volatile("cp.async.wait_group 0;");
}
__device__ __forceinline__ void cp_wait1() {
    asm volatile("cp.async.wait_group 1;");
}
__device__ __forceinline__ uint32_t f2tf32(float f) {
    uint32_t u;
    asm("cvt.rna.tf32.f32 %0, %1;" : "=r"(u) : "f"(f));
    return u;
}
__device__ __forceinline__ void mma_tf32(float* d, const uint32_t* a, const uint32_t* b) {
    asm volatile(
        "mma.sync.aligned.m16n8k8.row.col.f32.tf32.tf32.f32 "
        "{%0,%1,%2,%3}, {%4,%5,%6,%7}, {%8,%9}, {%0,%1,%2,%3};"
        : "+f"(d[0]), "+f"(d[1]), "+f"(d[2]), "+f"(d[3])
        : "r"(a[0]), "r"(a[1]), "r"(a[2]), "r"(a[3]), "r"(b[0]), "r"(b[1]));
}

// ---------------------------------------------------------------------------
// Grid-stride tf32 (rna) rounding copy, float4
// ---------------------------------------------------------------------------
__global__ __launch_bounds__(256) void round4_kernel(
    const float4* __restrict__ src, float4* __restrict__ dst, int n4)
{
    const int stride = gridDim.x * blockDim.x;
    for (int i = blockIdx.x * blockDim.x + threadIdx.x; i < n4; i += stride) {
        float4 v = src[i];
        v.x = __uint_as_float(f2tf32(v.x));
        v.y = __uint_as_float(f2tf32(v.y));
        v.z = __uint_as_float(f2tf32(v.z));
        v.w = __uint_as_float(f2tf32(v.w));
        dst[i] = v;
    }
}

// ---------------------------------------------------------------------------
// addmm: C[M,1024] = A[M,1024] @ W[1024,1024]^T + bias (optional *clamp(rs))
// Inputs A, W are PRE-ROUNDED to tf32 -> fragment loads are pure LDS.
// rflag != 0: round outputs to tf32 (for K/V).
// ---------------------------------------------------------------------------
#define KSTR 36
#define STAGE_F (128 * KSTR)

__global__ __launch_bounds__(256, 2) void addmm_tf32(
    const float* __restrict__ Ag, const float* __restrict__ Wg,
    const float* __restrict__ bias, const float* __restrict__ scale_ptr,
    float* __restrict__ C, int rflag)
{
    extern __shared__ float smf[];
    const int K = 1024;
    const int tid  = threadIdx.x;
    const int lane = tid & 31;
    const int wid  = tid >> 5;
    const int wm   = wid & 1;
    const int wn   = wid >> 1;
    const int bm   = blockIdx.x * 128;
    const int bn   = blockIdx.y * 128;

    const int kv = tid & 7;
    const int rg = tid >> 3;

    const float* Aptr = Ag + (size_t)(bm + rg) * K + kv * 4;
    const float* Wptr = Wg + (size_t)(bn + rg) * K + kv * 4;

    const uint32_t sA = (uint32_t)__cvta_generic_to_shared(smf);
    const uint32_t sB = sA + 2u * STAGE_F * 4u;

    auto issue = [&](int kt, int buf) {
        const int kk = kt * 32;
        const uint32_t a_s = sA + (uint32_t)buf * STAGE_F * 4u;
        const uint32_t b_s = sB + (uint32_t)buf * STAGE_F * 4u;
        #pragma unroll
        for (int j = 0; j < 4; ++j) {
            const int row = rg + j * 32;
            cp_async16(a_s + (uint32_t)(row * KSTR + kv * 4) * 4u,
                       Aptr + (size_t)j * 32 * K + kk);
            cp_async16(b_s + (uint32_t)(row * KSTR + kv * 4) * 4u,
                       Wptr + (size_t)j * 32 * K + kk);
        }
    };

    float acc[4][4][4] = {};

    issue(0, 0);
    cp_commit();

    const int KT = K / 32;
    for (int kt = 0; kt < KT; ++kt) {
        cp_wait0();
        __syncthreads();
        if (kt + 1 < KT) {
            issue(kt + 1, (kt + 1) & 1);
            cp_commit();
        }
        const uint32_t* As = (const uint32_t*)(smf + (kt & 1) * STAGE_F);
        const uint32_t* Bs = (const uint32_t*)(smf + 2 * STAGE_F + (kt & 1) * STAGE_F);
        const int r = lane >> 2, c = lane & 3;

        #pragma unroll
        for (int ks = 0; ks < 4; ++ks) {
            uint32_t a[4][4], b[4][2];
            #pragma unroll
            for (int mt = 0; mt < 4; ++mt) {
                const uint32_t* base = As + (wm * 64 + mt * 16 + r) * KSTR + ks * 8 + c;
                a[mt][0] = base[0];
                a[mt][1] = base[8 * KSTR];
                a[mt][2] = base[4];
                a[mt][3] = base[8 * KSTR + 4];
            }
            #pragma unroll
            for (int nt = 0; nt < 4; ++nt) {
                const uint32_t* base = Bs + (wn * 32 + nt * 8 + r) * KSTR + ks * 8 + c;
                b[nt][0] = base[0];
                b[nt][1] = base[4];
            }
            #pragma unroll
            for (int mt = 0; mt < 4; ++mt)
                #pragma unroll
                for (int nt = 0; nt < 4; ++nt)
                    mma_tf32(acc[mt][nt], a[mt], b[nt]);
        }
        __syncthreads();
    }

    float scl = 1.0f;
    if (scale_ptr) scl = fminf(fmaxf(*scale_ptr, 0.0f), 0.3f);

    const int r = lane >> 2;
    const int c2 = (lane & 3) * 2;
    #pragma unroll
    for (int mt = 0; mt < 4; ++mt) {
        const int row0 = bm + wm * 64 + mt * 16 + r;
        #pragma unroll
        for (int nt = 0; nt < 4; ++nt) {
            const int col = bn + wn * 32 + nt * 8 + c2;
            const float b0 = bias[col], b1 = bias[col + 1];
            float4 vals;
            vals.x = (acc[mt][nt][0] + b0) * scl;
            vals.y = (acc[mt][nt][1] + b1) * scl;
            vals.z = (acc[mt][nt][2] + b0) * scl;
            vals.w = (acc[mt][nt][3] + b1) * scl;
            if (rflag) {
                vals.x = __uint_as_float(f2tf32(vals.x));
                vals.y = __uint_as_float(f2tf32(vals.y));
                vals.z = __uint_as_float(f2tf32(vals.z));
                vals.w = __uint_as_float(f2tf32(vals.w));
            }
            *reinterpret_cast<float2*>(&C[(size_t)row0 * 1024 + col]) =
                make_float2(vals.x, vals.y);
            *reinterpret_cast<float2*>(&C[(size_t)(row0 + 8) * 1024 + col]) =
                make_float2(vals.z, vals.w);
        }
    }
}

// ---------------------------------------------------------------------------
// Tensor-core flash attention.
// Block = 128 queries x 1 head: 8 warps, warp = 16 queries.
// K/V arrive PRE-ROUNDED to tf32 (projection epilogue) -> no conversion pass.
// QK^T uses tf32x2 (qh*k + ql*k; Q hi/lo in registers), PV plain tf32.
// P round-trips through per-warp smem. ctx written tf32-rounded for O-GEMM.
// ---------------------------------------------------------------------------
#define QSTR 68
#define KVCH 64
#define KVW (KVCH * QSTR)

__global__ __launch_bounds__(256) void attn_mma(
    const int* __restrict__ amask, float* __restrict__ ctx)
{
    extern __shared__ float sm[];
    float* sQ    = sm;                         // 128*68 (reused as sP)
    float* sKt   = sm + 128 * QSTR;            // 2 bufs, tf32 bits
    float* sVt   = sKt + 2 * KVW;              // 2 bufs, tf32 bits
    int*   sMi   = (int*)(sVt + 2 * KVW);      // 2 * 64 ints

    const int s0  = blockIdx.x * 128;
    const int nh  = blockIdx.y;
    const int b   = blockIdx.z;
    const int tid = threadIdx.x;
    const int lane = tid & 31;
    const int wid  = tid >> 5;
    const int r = lane >> 2;
    const int c = lane & 3;

    const uint32_t sQa = (uint32_t)__cvta_generic_to_shared(sQ);
    const uint32_t sKa = (uint32_t)__cvta_generic_to_shared(sKt);
    const uint32_t sVa = (uint32_t)__cvta_generic_to_shared(sVt);
    const uint32_t sMa = (uint32_t)__cvta_generic_to_shared(sMi);

    // ---- issue Q tile load (group 0): 128 rows x 16 float4 ----
    #pragma unroll
    for (int i = 0; i < 8; ++i) {
        const int it = tid + i * 256;
        const int row = it >> 4, col = it & 15;
        cp_async16(sQa + (uint32_t)(row * QSTR + col * 4) * 4u,
                   &g_q[(size_t)(b * Ss + s0 + row) * Hh + nh * HDd + col * 4]);
    }
    cp_commit();

    auto load_kv = [&](int ch, int buf) {
        const int a0 = ch * KVCH;
        const uint32_t ko = sKa + (uint32_t)buf * KVW * 4u;
        const uint32_t vo = sVa + (uint32_t)buf * KVW * 4u;
        #pragma unroll
        for (int i = 0; i < 4; ++i) {
            const int it = tid + i * 256;
            const int row = it >> 4, col = it & 15;
            const size_t g = (size_t)(b * Aa + a0 + row) * Hh + nh * HDd + col * 4;
            cp_async16(ko + (uint32_t)(row * QSTR + col * 4) * 4u, &g_k[g]);
            cp_async16(vo + (uint32_t)(row * QSTR + col * 4) * 4u, &g_v[g]);
        }
        if (tid < 16)
            cp_async16(sMa + (uint32_t)buf * 256u + tid * 16u,
                       &amask[b * Aa + a0 + tid * 4]);
    };

    load_kv(0, 0);   // group 1
    cp_commit();

    cp_wait1();      // Q ready
    __syncthreads();

    // ---- build Q fragments (hi/lo split; both live in registers) ----
    uint32_t qh[8][4], ql[8][4];
    {
        const float* qb = sQ + (wid * 16) * QSTR;
        #pragma unroll
        for (int kt = 0; kt < 8; ++kt) {
            #pragma unroll
            for (int j = 0; j < 4; ++j) {
                const int rr = r + (j & 1) * 8;
                const int cc = kt * 8 + c + (j >> 1) * 4;
                const float f = qb[rr * QSTR + cc];
                const uint32_t hi = f2tf32(f);
                qh[kt][j] = hi;
                ql[kt][j] = f2tf32(f - __uint_as_float(hi));
            }
        }
    }
    __syncthreads();   // all warps done reading sQ; region becomes sP

    float m0 = -1e30f, m1 = -1e30f, l0 = 0.0f, l1 = 0.0f;
    float o[8][4] = {};
    float* sP = sQ + (wid * 16) * QSTR;   // per-warp private 16x68 region

    for (int ch = 0; ch < 8; ++ch) {
        const int buf = ch & 1;
        cp_wait0();
        __syncthreads();
        if (ch < 7) { load_kv(ch + 1, buf ^ 1); cp_commit(); }

        const uint32_t* Kh = (const uint32_t*)(sKt + buf * KVW);
        const uint32_t* Vt = (const uint32_t*)(sVt + buf * KVW);
        const int* bM = sMi + buf * KVCH;

        // ---- S = Q K^T (tf32x2: qh*k + ql*k) ----
        float s[8][4] = {};
        #pragma unroll
        for (int kt = 0; kt < 8; ++kt) {
            #pragma unroll
            for (int nt = 0; nt < 8; ++nt) {
                const int base = (nt * 8 + r) * QSTR + kt * 8 + c;
                uint32_t bh[2] = { Kh[base], Kh[base + 4] };
                mma_tf32(s[nt], qh[kt], bh);
                mma_tf32(s[nt], ql[kt], bh);
            }
        }

        // ---- scale + clip + mask, row maxima ----
        float rm0 = -1e30f, rm1 = -1e30f;
        #pragma unroll
        for (int nt = 0; nt < 8; ++nt) {
            const int mk0 = bM[nt * 8 + 2 * c];
            const int mk1 = bM[nt * 8 + 2 * c + 1];
            #pragma unroll
            for (int j = 0; j < 4; ++j) {
                float sc = fminf(fmaxf(s[nt][j] * 0.125f, -50.0f), 50.0f);
                const int mk = (j & 1) ? mk1 : mk0;
                if (mk <= 0) sc = -50.0f;
                s[nt][j] = sc;
            }
            rm0 = fmaxf(rm0, fmaxf(s[nt][0], s[nt][1]));
            rm1 = fmaxf(rm1, fmaxf(s[nt][2], s[nt][3]));
        }
        rm0 = fmaxf(rm0, __shfl_xor_sync(0xffffffffu, rm0, 1));
        rm0 = fmaxf(rm0, __shfl_xor_sync(0xffffffffu, rm0, 2));
        rm1 = fmaxf(rm1, __shfl_xor_sync(0xffffffffu, rm1, 1));
        rm1 = fmaxf(rm1, __shfl_xor_sync(0xffffffffu, rm1, 2));

        const float nm0 = fmaxf(m0, rm0);
        const float nm1 = fmaxf(m1, rm1);
        const float corr0 = __expf(m0 - nm0);
        const float corr1 = __expf(m1 - nm1);
        m0 = nm0; m1 = nm1;

        float ps0 = 0.0f, ps1 = 0.0f;
        #pragma unroll
        for (int nt = 0; nt < 8; ++nt) {
            s[nt][0] = __expf(s[nt][0] - nm0);
            s[nt][1] = __expf(s[nt][1] - nm0);
            s[nt][2] = __expf(s[nt][2] - nm1);
            s[nt][3] = __expf(s[nt][3] - nm1);
            ps0 += s[nt][0] + s[nt][1];
            ps1 += s[nt][2] + s[nt][3];
        }
        ps0 += __shfl_xor_sync(0xffffffffu, ps0, 1);
        ps0 += __shfl_xor_sync(0xffffffffu, ps0, 2);
        ps1 += __shfl_xor_sync(0xffffffffu, ps1, 1);
        ps1 += __shfl_xor_sync(0xffffffffu, ps1, 2);
        l0 = l0 * corr0 + ps0;
        l1 = l1 * corr1 + ps1;

        #pragma unroll
        for (int nt = 0; nt < 8; ++nt) {
            o[nt][0] *= corr0; o[nt][1] *= corr0;
            o[nt][2] *= corr1; o[nt][3] *= corr1;
        }

        // ---- P -> per-warp smem (D-frag -> A-frag layout fix) ----
        #pragma unroll
        for (int nt = 0; nt < 8; ++nt) {
            *reinterpret_cast<float2*>(&sP[r * QSTR + nt * 8 + 2 * c]) =
                make_float2(s[nt][0], s[nt][1]);
            *reinterpret_cast<float2*>(&sP[(r + 8) * QSTR + nt * 8 + 2 * c]) =
                make_float2(s[nt][2], s[nt][3]);
        }
        __syncwarp();

        // ---- O += P V (tf32) ----
        #pragma unroll
        for (int kt = 0; kt < 8; ++kt) {
            uint32_t ap[4];
            ap[0] = f2tf32(sP[r * QSTR + kt * 8 + c]);
            ap[1] = f2tf32(sP[(r + 8) * QSTR + kt * 8 + c]);
            ap[2] = f2tf32(sP[r * QSTR + kt * 8 + c + 4]);
            ap[3] = f2tf32(sP[(r + 8) * QSTR + kt * 8 + c + 4]);
            #pragma unroll
            for (int nt = 0; nt < 8; ++nt) {
                uint32_t bv[2];
                bv[0] = Vt[(kt * 8 + c) * QSTR + nt * 8 + r];
                bv[1] = Vt[(kt * 8 + c + 4) * QSTR + nt * 8 + r];
                mma_tf32(o[nt], ap, bv);
            }
        }
        __syncwarp();
    }

    // ---- finalize + store (tf32-rounded for the O-GEMM) ----
    const float inv0 = 1.0f / l0;
    const float inv1 = 1.0f / l1;
    const int row0 = s0 + wid * 16 + r;
    #pragma unroll
    for (int nt = 0; nt < 8; ++nt) {
        const int col = nh * HDd + nt * 8 + 2 * c;
        float2 w0 = make_float2(__uint_as_float(f2tf32(o[nt][0] * inv0)),
                                __uint_as_float(f2tf32(o[nt][1] * inv0)));
        float2 w1 = make_float2(__uint_as_float(f2tf32(o[nt][2] * inv1)),
                                __uint_as_float(f2tf32(o[nt][3] * inv1)));
        *reinterpret_cast<float2*>(&ctx[(size_t)(b * Ss + row0) * Hh + col]) = w0;
        *reinterpret_cast<float2*>(&ctx[(size_t)(b * Ss + row0 + 8) * Hh + col]) = w1;
    }
}

// ---------------------------------------------------------------------------
// Row LayerNorm over H=1024
// ---------------------------------------------------------------------------
__global__ __launch_bounds__(256) void ln_kernel(
    const float* __restrict__ X, const float* __restrict__ gamma,
    const float* __restrict__ beta, float* __restrict__ out)
{
    __shared__ float red[8];
    const int row = blockIdx.x;
    const int tid = threadIdx.x;

    const float4 v = reinterpret_cast<const float4*>(X + (size_t)row * Hh)[tid];
    float sum = v.x + v.y + v.z + v.w;
    #pragma unroll
    for (int o = 16; o; o >>= 1) sum += __shfl_xor_sync(0xffffffffu, sum, o);
    if ((tid & 31) == 0) red[tid >> 5] = sum;
    __syncthreads();
    float tot = 0.0f;
    #pragma unroll
    for (int i = 0; i < 8; ++i) tot += red[i];
    const float mu = tot * (1.0f / Hh);

    const float dx = v.x - mu, dy = v.y - mu, dz = v.z - mu, dw = v.w - mu;
    float sq = dx * dx + dy * dy + dz * dz + dw * dw;
    #pragma unroll
    for (int o = 16; o; o >>= 1) sq += __shfl_xor_sync(0xffffffffu, sq, o);
    __syncthreads();
    if ((tid & 31) == 0) red[tid >> 5] = sq;
    __syncthreads();
    float tot2 = 0.0f;
    #pragma unroll
    for (int i = 0; i < 8; ++i) tot2 += red[i];
    const float var = tot2 * (1.0f / Hh);
    const float rstd = rsqrtf(var + 1e-5f);

    const float4 gm = reinterpret_cast<const float4*>(gamma)[tid];
    const float4 bt = reinterpret_cast<const float4*>(beta)[tid];
    float4 o;
    o.x = dx * rstd * gm.x + bt.x;
    o.y = dy * rstd * gm.y + bt.y;
    o.z = dz * rstd * gm.z + bt.z;
    o.w = dw * rstd * gm.w + bt.w;
    reinterpret_cast<float4*>(out + (size_t)row * Hh)[tid] = o;
}

// ---------------------------------------------------------------------------
extern "C" void kernel_launch(void* const* d_in, const int* in_sizes, int n_in,
                              void* d_out, int out_size)
{
    const float* hs    = (const float*)d_in[0];
    const float* at    = (const float*)d_in[1];
    const int*   am    = (const int*)d_in[2];
    const float* Wq    = (const float*)d_in[3];
    const float* bq    = (const float*)d_in[4];
    const float* Wk    = (const float*)d_in[5];
    const float* bk    = (const float*)d_in[6];
    const float* Wv    = (const float*)d_in[7];
    const float* bv    = (const float*)d_in[8];
    const float* Wo    = (const float*)d_in[9];
    const float* bo    = (const float*)d_in[10];
    const float* gamma = (const float*)d_in[11];
    const float* beta  = (const float*)d_in[12];
    const float* rs    = (const float*)d_in[13];
    float* out = (float*)d_out;

    float *q, *k, *v, *ctx, *hsr, *atr, *wr;
    cudaGetSymbolAddress((void**)&q,   g_q);
    cudaGetSymbolAddress((void**)&k,   g_k);
    cudaGetSymbolAddress((void**)&v,   g_v);
    cudaGetSymbolAddress((void**)&ctx, g_ctx);
    cudaGetSymbolAddress((void**)&hsr, g_hsr);
    cudaGetSymbolAddress((void**)&atr, g_atr);
    cudaGetSymbolAddress((void**)&wr,  g_wr);

    const dim3 blk(256);
    const size_t WN = (size_t)Hh * Hh;  // 1M

    // ---- prep: tf32-round all GEMM operands once ----
    round4_kernel<<<592, blk>>>((const float4*)hs, (float4*)hsr,
                                (int)((size_t)Bb * Ss * Hh / 4));
    round4_kernel<<<148, blk>>>((const float4*)at, (float4*)atr,
                                (int)((size_t)Bb * Aa * Hh / 4));
    round4_kernel<<<148, blk>>>((const float4*)Wq, (float4*)(wr + 0 * WN), (int)(WN / 4));
    round4_kernel<<<148, blk>>>((const float4*)Wk, (float4*)(wr + 1 * WN), (int)(WN / 4));
    round4_kernel<<<148, blk>>>((const float4*)Wv, (float4*)(wr + 2 * WN), (int)(WN / 4));
    round4_kernel<<<148, blk>>>((const float4*)Wo, (float4*)(wr + 3 * WN), (int)(WN / 4));

    const int gemm_smem = 4 * STAGE_F * sizeof(float);
    const int attn_smem = (128 * QSTR + 4 * KVW) * sizeof(float)
                        + 2 * KVCH * sizeof(int);
    static int attr_done = 0;
    if (!attr_done) {
        cudaFuncSetAttribute(addmm_tf32, cudaFuncAttributeMaxDynamicSharedMemorySize, gemm_smem);
        cudaFuncSetAttribute(attn_mma, cudaFuncAttributeMaxDynamicSharedMemorySize, attn_smem);
        attr_done = 1;
    }

    // Projections (K/V outputs rounded to tf32 in epilogue)
    addmm_tf32<<<dim3((Bb * Ss) / 128, Hh / 128), blk, gemm_smem>>>(
        hsr, wr + 0 * WN, bq, nullptr, q, 0);
    addmm_tf32<<<dim3((Bb * Aa) / 128, Hh / 128), blk, gemm_smem>>>(
        atr, wr + 1 * WN, bk, nullptr, k, 1);
    addmm_tf32<<<dim3((Bb * Aa) / 128, Hh / 128), blk, gemm_smem>>>(
        atr, wr + 2 * WN, bv, nullptr, v, 1);

    // Attention (tensor-core; ctx written tf32-rounded)
    attn_mma<<<dim3(Ss / 128, NHh, Bb), blk, attn_smem>>>(am, ctx);

    // Output projection (+bias, * clamp(rs,0,0.3)) into reused q buffer
    addmm_tf32<<<dim3((Bb * Ss) / 128, Hh / 128), blk, gemm_smem>>>(
        ctx, wr + 3 * WN, bo, rs, q, 0);

    // LayerNorm -> final output
    ln_kernel<<<dim3(Bb * Ss), blk>>>(q, gamma, beta, out);
}

// round 7
// speedup vs baseline: 4.5832x; 1.1026x over previous
#include <cuda_runtime.h>
#include <math.h>
#include <stdint.h>

#define Bb 4
#define Ss 4096
#define Aa 512
#define Hh 1024
#define NHh 16
#define HDd 64

// Scratch (device globals: allocation-free rule)
__device__ float g_q[(size_t)Bb * Ss * Hh];    // q (tf32-rounded), later reused as delta
__device__ float g_k[(size_t)Bb * Aa * Hh];    // tf32-rounded
__device__ float g_v[(size_t)Bb * Aa * Hh];    // tf32-rounded
__device__ float g_ctx[(size_t)Bb * Ss * Hh];  // tf32-rounded
__device__ float g_hsr[(size_t)Bb * Ss * Hh];  // tf32-rounded hidden_states
__device__ float g_atr[(size_t)Bb * Aa * Hh];  // tf32-rounded audio_tokens
__device__ float g_wr[(size_t)4 * Hh * Hh];    // tf32-rounded Wq,Wk,Wv,Wo

// ---------------------------------------------------------------------------
// Helpers
// ---------------------------------------------------------------------------
__device__ __forceinline__ void cp_async16(uint32_t s, const void* g) {
    asm volatile("cp.async.cg.shared.global [%0], [%1], 16;" :: "r"(s), "l"(g));
}
__device__ __forceinline__ void cp_commit() {
    asm volatile("cp.async.commit_group;");
}
__device__ __forceinline__ void cp_wait0() {
    asm volatile("cp.async.wait_group 0;");
}
__device__ __forceinline__ void cp_wait1() {
    asm volatile("cp.async.wait_group 1;");
}
__device__ __forceinline__ uint32_t f2tf32(float f) {
    uint32_t u;
    asm("cvt.rna.tf32.f32 %0, %1;" : "=r"(u) : "f"(f));
    return u;
}
__device__ __forceinline__ void mma_tf32(float* d, const uint32_t* a, const uint32_t* b) {
    asm volatile(
        "mma.sync.aligned.m16n8k8.row.col.f32.tf32.tf32.f32 "
        "{%0,%1,%2,%3}, {%4,%5,%6,%7}, {%8,%9}, {%0,%1,%2,%3};"
        : "+f"(d[0]), "+f"(d[1]), "+f"(d[2]), "+f"(d[3])
        : "r"(a[0]), "r"(a[1]), "r"(a[2]), "r"(a[3]), "r"(b[0]), "r"(b[1]));
}

// ---------------------------------------------------------------------------
// Grid-stride tf32 (rna) rounding copy, float4
// ---------------------------------------------------------------------------
__global__ __launch_bounds__(256) void round4_kernel(
    const float4* __restrict__ src, float4* __restrict__ dst, int n4)
{
    const int stride = gridDim.x * blockDim.x;
    for (int i = blockIdx.x * blockDim.x + threadIdx.x; i < n4; i += stride) {
        float4 v = src[i];
        v.x = __uint_as_float(f2tf32(v.x));
        v.y = __uint_as_float(f2tf32(v.y));
        v.z = __uint_as_float(f2tf32(v.z));
        v.w = __uint_as_float(f2tf32(v.w));
        dst[i] = v;
    }
}

// ---------------------------------------------------------------------------
// addmm: C[M,1024] = A[M,1024] @ W[1024,1024]^T + bias (optional *clamp(rs))
// Inputs A, W are PRE-ROUNDED to tf32 -> fragment loads are pure LDS.
// rflag != 0: round outputs to tf32 (for Q/K/V).
// ---------------------------------------------------------------------------
#define KSTR 36
#define STAGE_F (128 * KSTR)

__global__ __launch_bounds__(256, 2) void addmm_tf32(
    const float* __restrict__ Ag, const float* __restrict__ Wg,
    const float* __restrict__ bias, const float* __restrict__ scale_ptr,
    float* __restrict__ C, int rflag)
{
    extern __shared__ float smf[];
    const int K = 1024;
    const int tid  = threadIdx.x;
    const int lane = tid & 31;
    const int wid  = tid >> 5;
    const int wm   = wid & 1;
    const int wn   = wid >> 1;
    const int bm   = blockIdx.x * 128;
    const int bn   = blockIdx.y * 128;

    const int kv = tid & 7;
    const int rg = tid >> 3;

    const float* Aptr = Ag + (size_t)(bm + rg) * K + kv * 4;
    const float* Wptr = Wg + (size_t)(bn + rg) * K + kv * 4;

    const uint32_t sA = (uint32_t)__cvta_generic_to_shared(smf);
    const uint32_t sB = sA + 2u * STAGE_F * 4u;

    auto issue = [&](int kt, int buf) {
        const int kk = kt * 32;
        const uint32_t a_s = sA + (uint32_t)buf * STAGE_F * 4u;
        const uint32_t b_s = sB + (uint32_t)buf * STAGE_F * 4u;
        #pragma unroll
        for (int j = 0; j < 4; ++j) {
            const int row = rg + j * 32;
            cp_async16(a_s + (uint32_t)(row * KSTR + kv * 4) * 4u,
                       Aptr + (size_t)j * 32 * K + kk);
            cp_async16(b_s + (uint32_t)(row * KSTR + kv * 4) * 4u,
                       Wptr + (size_t)j * 32 * K + kk);
        }
    };

    float acc[4][4][4] = {};

    issue(0, 0);
    cp_commit();

    const int KT = K / 32;
    for (int kt = 0; kt < KT; ++kt) {
        cp_wait0();
        __syncthreads();
        if (kt + 1 < KT) {
            issue(kt + 1, (kt + 1) & 1);
            cp_commit();
        }
        const uint32_t* As = (const uint32_t*)(smf + (kt & 1) * STAGE_F);
        const uint32_t* Bs = (const uint32_t*)(smf + 2 * STAGE_F + (kt & 1) * STAGE_F);
        const int r = lane >> 2, c = lane & 3;

        #pragma unroll
        for (int ks = 0; ks < 4; ++ks) {
            uint32_t a[4][4], b[4][2];
            #pragma unroll
            for (int mt = 0; mt < 4; ++mt) {
                const uint32_t* base = As + (wm * 64 + mt * 16 + r) * KSTR + ks * 8 + c;
                a[mt][0] = base[0];
                a[mt][1] = base[8 * KSTR];
                a[mt][2] = base[4];
                a[mt][3] = base[8 * KSTR + 4];
            }
            #pragma unroll
            for (int nt = 0; nt < 4; ++nt) {
                const uint32_t* base = Bs + (wn * 32 + nt * 8 + r) * KSTR + ks * 8 + c;
                b[nt][0] = base[0];
                b[nt][1] = base[4];
            }
            #pragma unroll
            for (int mt = 0; mt < 4; ++mt)
                #pragma unroll
                for (int nt = 0; nt < 4; ++nt)
                    mma_tf32(acc[mt][nt], a[mt], b[nt]);
        }
        __syncthreads();
    }

    float scl = 1.0f;
    if (scale_ptr) scl = fminf(fmaxf(*scale_ptr, 0.0f), 0.3f);

    const int r = lane >> 2;
    const int c2 = (lane & 3) * 2;
    #pragma unroll
    for (int mt = 0; mt < 4; ++mt) {
        const int row0 = bm + wm * 64 + mt * 16 + r;
        #pragma unroll
        for (int nt = 0; nt < 4; ++nt) {
            const int col = bn + wn * 32 + nt * 8 + c2;
            const float b0 = bias[col], b1 = bias[col + 1];
            float4 vals;
            vals.x = (acc[mt][nt][0] + b0) * scl;
            vals.y = (acc[mt][nt][1] + b1) * scl;
            vals.z = (acc[mt][nt][2] + b0) * scl;
            vals.w = (acc[mt][nt][3] + b1) * scl;
            if (rflag) {
                vals.x = __uint_as_float(f2tf32(vals.x));
                vals.y = __uint_as_float(f2tf32(vals.y));
                vals.z = __uint_as_float(f2tf32(vals.z));
                vals.w = __uint_as_float(f2tf32(vals.w));
            }
            *reinterpret_cast<float2*>(&C[(size_t)row0 * 1024 + col]) =
                make_float2(vals.x, vals.y);
            *reinterpret_cast<float2*>(&C[(size_t)(row0 + 8) * 1024 + col]) =
                make_float2(vals.z, vals.w);
        }
    }
}

// ---------------------------------------------------------------------------
// Tensor-core flash attention.
// Block = 128 queries x 1 head: 8 warps, warp = 16 queries, 2 CTAs/SM.
// Q/K/V all arrive PRE-ROUNDED to tf32 -> every fragment load is a raw
// uint32 LDS; zero cvt in the QK/PV loops. QK^T single tf32, PV tf32 with
// P rounded at the smem store. P round-trips through per-warp smem.
// ---------------------------------------------------------------------------
#define QSTR 68
#define KVCH 64
#define KVW (KVCH * QSTR)

__global__ __launch_bounds__(256, 2) void attn_mma(
    const int* __restrict__ amask, float* __restrict__ ctx)
{
    extern __shared__ float sm[];
    float* sQ    = sm;                         // 128*68 (reused as sP)
    float* sKt   = sm + 128 * QSTR;            // 2 bufs, tf32 bits
    float* sVt   = sKt + 2 * KVW;              // 2 bufs, tf32 bits
    int*   sMi   = (int*)(sVt + 2 * KVW);      // 2 * 64 ints

    const int s0  = blockIdx.x * 128;
    const int nh  = blockIdx.y;
    const int b   = blockIdx.z;
    const int tid = threadIdx.x;
    const int lane = tid & 31;
    const int wid  = tid >> 5;
    const int r = lane >> 2;
    const int c = lane & 3;

    const uint32_t sQa = (uint32_t)__cvta_generic_to_shared(sQ);
    const uint32_t sKa = (uint32_t)__cvta_generic_to_shared(sKt);
    const uint32_t sVa = (uint32_t)__cvta_generic_to_shared(sVt);
    const uint32_t sMa = (uint32_t)__cvta_generic_to_shared(sMi);

    // ---- issue Q tile load (group 0): 128 rows x 16 float4 ----
    #pragma unroll
    for (int i = 0; i < 8; ++i) {
        const int it = tid + i * 256;
        const int row = it >> 4, col = it & 15;
        cp_async16(sQa + (uint32_t)(row * QSTR + col * 4) * 4u,
                   &g_q[(size_t)(b * Ss + s0 + row) * Hh + nh * HDd + col * 4]);
    }
    cp_commit();

    auto load_kv = [&](int ch, int buf) {
        const int a0 = ch * KVCH;
        const uint32_t ko = sKa + (uint32_t)buf * KVW * 4u;
        const uint32_t vo = sVa + (uint32_t)buf * KVW * 4u;
        #pragma unroll
        for (int i = 0; i < 4; ++i) {
            const int it = tid + i * 256;
            const int row = it >> 4, col = it & 15;
            const size_t g = (size_t)(b * Aa + a0 + row) * Hh + nh * HDd + col * 4;
            cp_async16(ko + (uint32_t)(row * QSTR + col * 4) * 4u, &g_k[g]);
            cp_async16(vo + (uint32_t)(row * QSTR + col * 4) * 4u, &g_v[g]);
        }
        if (tid < 16)
            cp_async16(sMa + (uint32_t)buf * 256u + tid * 16u,
                       &amask[b * Aa + a0 + tid * 4]);
    };

    load_kv(0, 0);   // group 1
    cp_commit();

    cp_wait1();      // Q ready
    __syncthreads();

    // ---- Q fragments: raw uint32 (pre-rounded tf32 bits) ----
    uint32_t qh[8][4];
    {
        const uint32_t* qb = (const uint32_t*)(sQ + (wid * 16) * QSTR);
        #pragma unroll
        for (int kt = 0; kt < 8; ++kt) {
            #pragma unroll
            for (int j = 0; j < 4; ++j) {
                const int rr = r + (j & 1) * 8;
                const int cc = kt * 8 + c + (j >> 1) * 4;
                qh[kt][j] = qb[rr * QSTR + cc];
            }
        }
    }
    __syncthreads();   // all warps done reading sQ; region becomes sP

    float m0 = -1e30f, m1 = -1e30f, l0 = 0.0f, l1 = 0.0f;
    float o[8][4] = {};
    float* sP = sQ + (wid * 16) * QSTR;   // per-warp private 16x68 region

    for (int ch = 0; ch < 8; ++ch) {
        const int buf = ch & 1;
        cp_wait0();
        __syncthreads();
        if (ch < 7) { load_kv(ch + 1, buf ^ 1); cp_commit(); }

        const uint32_t* Kh = (const uint32_t*)(sKt + buf * KVW);
        const uint32_t* Vt = (const uint32_t*)(sVt + buf * KVW);
        const int* bM = sMi + buf * KVCH;

        // ---- S = Q K^T (single tf32) ----
        float s[8][4] = {};
        #pragma unroll
        for (int kt = 0; kt < 8; ++kt) {
            #pragma unroll
            for (int nt = 0; nt < 8; ++nt) {
                const int base = (nt * 8 + r) * QSTR + kt * 8 + c;
                uint32_t bh[2] = { Kh[base], Kh[base + 4] };
                mma_tf32(s[nt], qh[kt], bh);
            }
        }

        // ---- scale + clip + mask, row maxima ----
        float rm0 = -1e30f, rm1 = -1e30f;
        #pragma unroll
        for (int nt = 0; nt < 8; ++nt) {
            const int mk0 = bM[nt * 8 + 2 * c];
            const int mk1 = bM[nt * 8 + 2 * c + 1];
            #pragma unroll
            for (int j = 0; j < 4; ++j) {
                float sc = fminf(fmaxf(s[nt][j] * 0.125f, -50.0f), 50.0f);
                const int mk = (j & 1) ? mk1 : mk0;
                if (mk <= 0) sc = -50.0f;
                s[nt][j] = sc;
            }
            rm0 = fmaxf(rm0, fmaxf(s[nt][0], s[nt][1]));
            rm1 = fmaxf(rm1, fmaxf(s[nt][2], s[nt][3]));
        }
        rm0 = fmaxf(rm0, __shfl_xor_sync(0xffffffffu, rm0, 1));
        rm0 = fmaxf(rm0, __shfl_xor_sync(0xffffffffu, rm0, 2));
        rm1 = fmaxf(rm1, __shfl_xor_sync(0xffffffffu, rm1, 1));
        rm1 = fmaxf(rm1, __shfl_xor_sync(0xffffffffu, rm1, 2));

        const float nm0 = fmaxf(m0, rm0);
        const float nm1 = fmaxf(m1, rm1);
        const float corr0 = __expf(m0 - nm0);
        const float corr1 = __expf(m1 - nm1);
        m0 = nm0; m1 = nm1;

        float ps0 = 0.0f, ps1 = 0.0f;
        #pragma unroll
        for (int nt = 0; nt < 8; ++nt) {
            s[nt][0] = __expf(s[nt][0] - nm0);
            s[nt][1] = __expf(s[nt][1] - nm0);
            s[nt][2] = __expf(s[nt][2] - nm1);
            s[nt][3] = __expf(s[nt][3] - nm1);
            ps0 += s[nt][0] + s[nt][1];
            ps1 += s[nt][2] + s[nt][3];
        }
        ps0 += __shfl_xor_sync(0xffffffffu, ps0, 1);
        ps0 += __shfl_xor_sync(0xffffffffu, ps0, 2);
        ps1 += __shfl_xor_sync(0xffffffffu, ps1, 1);
        ps1 += __shfl_xor_sync(0xffffffffu, ps1, 2);
        l0 = l0 * corr0 + ps0;
        l1 = l1 * corr1 + ps1;

        #pragma unroll
        for (int nt = 0; nt < 8; ++nt) {
            o[nt][0] *= corr0; o[nt][1] *= corr0;
            o[nt][2] *= corr1; o[nt][3] *= corr1;
        }

        // ---- P -> per-warp smem, rounded to tf32 at store ----
        #pragma unroll
        for (int nt = 0; nt < 8; ++nt) {
            *reinterpret_cast<float2*>(&sP[r * QSTR + nt * 8 + 2 * c]) =
                make_float2(__uint_as_float(f2tf32(s[nt][0])),
                            __uint_as_float(f2tf32(s[nt][1])));
            *reinterpret_cast<float2*>(&sP[(r + 8) * QSTR + nt * 8 + 2 * c]) =
                make_float2(__uint_as_float(f2tf32(s[nt][2])),
                            __uint_as_float(f2tf32(s[nt][3])));
        }
        __syncwarp();

        // ---- O += P V (tf32, pure LDS fragments) ----
        const uint32_t* sPu = (const uint32_t*)sP;
        #pragma unroll
        for (int kt = 0; kt < 8; ++kt) {
            uint32_t ap[4];
            ap[0] = sPu[r * QSTR + kt * 8 + c];
            ap[1] = sPu[(r + 8) * QSTR + kt * 8 + c];
            ap[2] = sPu[r * QSTR + kt * 8 + c + 4];
            ap[3] = sPu[(r + 8) * QSTR + kt * 8 + c + 4];
            #pragma unroll
            for (int nt = 0; nt < 8; ++nt) {
                uint32_t bv[2];
                bv[0] = Vt[(kt * 8 + c) * QSTR + nt * 8 + r];
                bv[1] = Vt[(kt * 8 + c + 4) * QSTR + nt * 8 + r];
                mma_tf32(o[nt], ap, bv);
            }
        }
        __syncwarp();
    }

    // ---- finalize + store (tf32-rounded for the O-GEMM) ----
    const float inv0 = 1.0f / l0;
    const float inv1 = 1.0f / l1;
    const int row0 = s0 + wid * 16 + r;
    #pragma unroll
    for (int nt = 0; nt < 8; ++nt) {
        const int col = nh * HDd + nt * 8 + 2 * c;
        float2 w0 = make_float2(__uint_as_float(f2tf32(o[nt][0] * inv0)),
                                __uint_as_float(f2tf32(o[nt][1] * inv0)));
        float2 w1 = make_float2(__uint_as_float(f2tf32(o[nt][2] * inv1)),
                                __uint_as_float(f2tf32(o[nt][3] * inv1)));
        *reinterpret_cast<float2*>(&ctx[(size_t)(b * Ss + row0) * Hh + col]) = w0;
        *reinterpret_cast<float2*>(&ctx[(size_t)(b * Ss + row0 + 8) * Hh + col]) = w1;
    }
}

// ---------------------------------------------------------------------------
// Row LayerNorm over H=1024
// ---------------------------------------------------------------------------
__global__ __launch_bounds__(256) void ln_kernel(
    const float* __restrict__ X, const float* __restrict__ gamma,
    const float* __restrict__ beta, float* __restrict__ out)
{
    __shared__ float red[8];
    const int row = blockIdx.x;
    const int tid = threadIdx.x;

    const float4 v = reinterpret_cast<const float4*>(X + (size_t)row * Hh)[tid];
    float sum = v.x + v.y + v.z + v.w;
    #pragma unroll
    for (int o = 16; o; o >>= 1) sum += __shfl_xor_sync(0xffffffffu, sum, o);
    if ((tid & 31) == 0) red[tid >> 5] = sum;
    __syncthreads();
    float tot = 0.0f;
    #pragma unroll
    for (int i = 0; i < 8; ++i) tot += red[i];
    const float mu = tot * (1.0f / Hh);

    const float dx = v.x - mu, dy = v.y - mu, dz = v.z - mu, dw = v.w - mu;
    float sq = dx * dx + dy * dy + dz * dz + dw * dw;
    #pragma unroll
    for (int o = 16; o; o >>= 1) sq += __shfl_xor_sync(0xffffffffu, sq, o);
    __syncthreads();
    if ((tid & 31) == 0) red[tid >> 5] = sq;
    __syncthreads();
    float tot2 = 0.0f;
    #pragma unroll
    for (int i = 0; i < 8; ++i) tot2 += red[i];
    const float var = tot2 * (1.0f / Hh);
    const float rstd = rsqrtf(var + 1e-5f);

    const float4 gm = reinterpret_cast<const float4*>(gamma)[tid];
    const float4 bt = reinterpret_cast<const float4*>(beta)[tid];
    float4 o;
    o.x = dx * rstd * gm.x + bt.x;
    o.y = dy * rstd * gm.y + bt.y;
    o.z = dz * rstd * gm.z + bt.z;
    o.w = dw * rstd * gm.w + bt.w;
    reinterpret_cast<float4*>(out + (size_t)row * Hh)[tid] = o;
}

// ---------------------------------------------------------------------------
extern "C" void kernel_launch(void* const* d_in, const int* in_sizes, int n_in,
                              void* d_out, int out_size)
{
    const float* hs    = (const float*)d_in[0];
    const float* at    = (const float*)d_in[1];
    const int*   am    = (const int*)d_in[2];
    const float* Wq    = (const float*)d_in[3];
    const float* bq    = (const float*)d_in[4];
    const float* Wk    = (const float*)d_in[5];
    const float* bk    = (const float*)d_in[6];
    const float* Wv    = (const float*)d_in[7];
    const float* bv    = (const float*)d_in[8];
    const float* Wo    = (const float*)d_in[9];
    const float* bo    = (const float*)d_in[10];
    const float* gamma = (const float*)d_in[11];
    const float* beta  = (const float*)d_in[12];
    const float* rs    = (const float*)d_in[13];
    float* out = (float*)d_out;

    float *q, *k, *v, *ctx, *hsr, *atr, *wr;
    cudaGetSymbolAddress((void**)&q,   g_q);
    cudaGetSymbolAddress((void**)&k,   g_k);
    cudaGetSymbolAddress((void**)&v,   g_v);
    cudaGetSymbolAddress((void**)&ctx, g_ctx);
    cudaGetSymbolAddress((void**)&hsr, g_hsr);
    cudaGetSymbolAddress((void**)&atr, g_atr);
    cudaGetSymbolAddress((void**)&wr,  g_wr);

    const dim3 blk(256);
    const size_t WN = (size_t)Hh * Hh;  // 1M

    // ---- prep: tf32-round all GEMM operands once (high-occupancy grids) ----
    const int n4_hs = (int)((size_t)Bb * Ss * Hh / 4);
    const int n4_at = (int)((size_t)Bb * Aa * Hh / 4);
    const int n4_w  = (int)(WN / 4);
    round4_kernel<<<(n4_hs + 1023) / 1024, blk>>>((const float4*)hs, (float4*)hsr, n4_hs);
    round4_kernel<<<(n4_at + 1023) / 1024, blk>>>((const float4*)at, (float4*)atr, n4_at);
    round4_kernel<<<(n4_w + 1023) / 1024, blk>>>((const float4*)Wq, (float4*)(wr + 0 * WN), n4_w);
    round4_kernel<<<(n4_w + 1023) / 1024, blk>>>((const float4*)Wk, (float4*)(wr + 1 * WN), n4_w);
    round4_kernel<<<(n4_w + 1023) / 1024, blk>>>((const float4*)Wv, (float4*)(wr + 2 * WN), n4_w);
    round4_kernel<<<(n4_w + 1023) / 1024, blk>>>((const float4*)Wo, (float4*)(wr + 3 * WN), n4_w);

    const int gemm_smem = 4 * STAGE_F * sizeof(float);
    const int attn_smem = (128 * QSTR + 4 * KVW) * sizeof(float)
                        + 2 * KVCH * sizeof(int);
    static int attr_done = 0;
    if (!attr_done) {
        cudaFuncSetAttribute(addmm_tf32, cudaFuncAttributeMaxDynamicSharedMemorySize, gemm_smem);
        cudaFuncSetAttribute(attn_mma, cudaFuncAttributeMaxDynamicSharedMemorySize, attn_smem);
        attr_done = 1;
    }

    // Projections (Q/K/V outputs rounded to tf32 in epilogue)
    addmm_tf32<<<dim3((Bb * Ss) / 128, Hh / 128), blk, gemm_smem>>>(
        hsr, wr + 0 * WN, bq, nullptr, q, 1);
    addmm_tf32<<<dim3((Bb * Aa) / 128, Hh / 128), blk, gemm_smem>>>(
        atr, wr + 1 * WN, bk, nullptr, k, 1);
    addmm_tf32<<<dim3((Bb * Aa) / 128, Hh / 128), blk, gemm_smem>>>(
        atr, wr + 2 * WN, bv, nullptr, v, 1);

    // Attention (tensor-core; ctx written tf32-rounded)
    attn_mma<<<dim3(Ss / 128, NHh, Bb), blk, attn_smem>>>(am, ctx);

    // Output projection (+bias, * clamp(rs,0,0.3)) into reused q buffer
    addmm_tf32<<<dim3((Bb * Ss) / 128, Hh / 128), blk, gemm_smem>>>(
        ctx, wr + 3 * WN, bo, rs, q, 0);

    // LayerNorm -> final output
    ln_kernel<<<dim3(Bb * Ss), blk>>>(q, gamma, beta, out);
}